// round 1
// baseline (speedup 1.0000x reference)
#include <cuda_runtime.h>

#define BATCH 8
#define SEQ   2048
#define DIM   1024
#define MTOT  (BATCH * SEQ)

// Scratch (device bss — no runtime allocation)
__device__ float g_q[(size_t)MTOT * DIM];                 // 64 MB
__device__ float g_k[(size_t)MTOT * DIM];                 // 64 MB
__device__ float g_v[(size_t)MTOT * DIM];                 // 64 MB
__device__ float g_s[(size_t)BATCH * SEQ * SEQ];          // 128 MB

// ---------------------------------------------------------------------------
// 128x128x8 SMEM-tiled fp32 GEMM core, 256 threads, 8x8 microtile per thread.
// A: row-major [.., lda], tile origin pre-offset by caller (by*128 rows).
// B: TRANSB=false -> row-major KxN  (tile origin offset by bx*128 cols)
//    TRANSB=true  -> row-major NxK, computes A @ B^T (origin offset bx*128 rows)
// C: row-major, tile origin pre-offset.
// ---------------------------------------------------------------------------
template <bool TRANSB>
__device__ __forceinline__ void gemm_body(const float* __restrict__ A,
                                          const float* __restrict__ Bm,
                                          float* __restrict__ C,
                                          int lda, int ldb, int ldc, int kIters)
{
    __shared__ float As[8][128];
    __shared__ float Bs[8][128];

    const int tid = threadIdx.x;
    const int tx  = tid & 15;   // 0..15 -> 8 output cols each
    const int ty  = tid >> 4;   // 0..15 -> 8 output rows each

    // A-tile load mapping: 128 rows x 8 cols, one float4 per thread
    const int ar = tid >> 1;          // 0..127
    const int ac = (tid & 1) * 4;     // 0 or 4
    // B-tile load mapping (non-trans): 8 rows x 128 cols
    const int bkk = tid >> 5;         // 0..7
    const int bn4 = (tid & 31) * 4;   // 0..124

    float acc[8][8];
#pragma unroll
    for (int i = 0; i < 8; i++)
#pragma unroll
        for (int j = 0; j < 8; j++) acc[i][j] = 0.0f;

    const float* Aptr = A + (size_t)ar * lda + ac;

    for (int kt = 0; kt < kIters; kt++) {
        // load A tile (transpose into As[k][m])
        float4 va = *(const float4*)(Aptr + (size_t)kt * 8);
        As[ac + 0][ar] = va.x;
        As[ac + 1][ar] = va.y;
        As[ac + 2][ar] = va.z;
        As[ac + 3][ar] = va.w;

        if (TRANSB) {
            float4 vb = *(const float4*)(Bm + (size_t)ar * ldb + kt * 8 + ac);
            Bs[ac + 0][ar] = vb.x;
            Bs[ac + 1][ar] = vb.y;
            Bs[ac + 2][ar] = vb.z;
            Bs[ac + 3][ar] = vb.w;
        } else {
            float4 vb = *(const float4*)(Bm + (size_t)(kt * 8 + bkk) * ldb + bn4);
            *(float4*)&Bs[bkk][bn4] = vb;
        }
        __syncthreads();

#pragma unroll
        for (int kk = 0; kk < 8; kk++) {
            float4 a0 = *(const float4*)&As[kk][ty * 8];
            float4 a1 = *(const float4*)&As[kk][ty * 8 + 4];
            float4 b0 = *(const float4*)&Bs[kk][tx * 8];
            float4 b1 = *(const float4*)&Bs[kk][tx * 8 + 4];
            float a[8] = {a0.x, a0.y, a0.z, a0.w, a1.x, a1.y, a1.z, a1.w};
            float b[8] = {b0.x, b0.y, b0.z, b0.w, b1.x, b1.y, b1.z, b1.w};
#pragma unroll
            for (int i = 0; i < 8; i++)
#pragma unroll
                for (int j = 0; j < 8; j++) acc[i][j] = fmaf(a[i], b[j], acc[i][j]);
        }
        __syncthreads();
    }

#pragma unroll
    for (int i = 0; i < 8; i++) {
        float* crow = C + (size_t)(ty * 8 + i) * ldc + tx * 8;
        *(float4*)(crow)     = make_float4(acc[i][0], acc[i][1], acc[i][2], acc[i][3]);
        *(float4*)(crow + 4) = make_float4(acc[i][4], acc[i][5], acc[i][6], acc[i][7]);
    }
}

// ---------------------------------------------------------------------------
// Kernel 1: Q/K/V projections. grid = (DIM/128, MTOT/128, 3)
// ---------------------------------------------------------------------------
__global__ void __launch_bounds__(256) qkv_gemm(const float* __restrict__ x,
                                                const float* __restrict__ Wq,
                                                const float* __restrict__ Wk,
                                                const float* __restrict__ Wv)
{
    const float* W   = (blockIdx.z == 0) ? Wq : (blockIdx.z == 1) ? Wk : Wv;
    float*       out = (blockIdx.z == 0) ? g_q : (blockIdx.z == 1) ? g_k : g_v;

    const float* A  = x + (size_t)blockIdx.y * 128 * DIM;
    const float* Bm = W + (size_t)blockIdx.x * 128;
    float*       C  = out + (size_t)blockIdx.y * 128 * DIM + (size_t)blockIdx.x * 128;
    gemm_body<false>(A, Bm, C, DIM, DIM, DIM, DIM / 8);
}

// ---------------------------------------------------------------------------
// Kernel 2: S = Q @ K^T per batch, skip tiles fully above the causal diagonal.
// grid = (SEQ/128, SEQ/128, BATCH)
// ---------------------------------------------------------------------------
__global__ void __launch_bounds__(256) scores_gemm()
{
    const int bx = blockIdx.x, by = blockIdx.y, b = blockIdx.z;
    if (bx > by) return;  // strictly above diagonal: never read downstream
    const float* A  = g_q + ((size_t)b * SEQ + (size_t)by * 128) * DIM;
    const float* Bm = g_k + ((size_t)b * SEQ + (size_t)bx * 128) * DIM;
    float*       C  = g_s + ((size_t)b * SEQ + (size_t)by * 128) * SEQ + (size_t)bx * 128;
    gemm_body<true>(A, Bm, C, DIM, DIM, SEQ, DIM / 8);
}

// ---------------------------------------------------------------------------
// Kernel 3: causal softmax over row i (valid length i+1), scale 1/sqrt(1024).
// Writes zeros for j > i so PV can run dense K-tiles through the diagonal.
// grid = MTOT blocks of 256 threads; <= 8 elements per thread.
// ---------------------------------------------------------------------------
__global__ void __launch_bounds__(256) softmax_causal()
{
    __shared__ float red[256];
    const int row = blockIdx.x;
    const int b = row >> 11;           // / SEQ
    const int i = row & (SEQ - 1);
    float* srow = g_s + ((size_t)b * SEQ + i) * SEQ;
    const int L = i + 1;
    const int tid = threadIdx.x;

    float v[8];
    float m = -INFINITY;
#pragma unroll
    for (int u = 0; u < 8; u++) {
        int j = tid + u * 256;
        v[u] = (j < L) ? srow[j] * 0.03125f : -INFINITY;
        m = fmaxf(m, v[u]);
    }
    red[tid] = m;
    __syncthreads();
#pragma unroll
    for (int s = 128; s > 0; s >>= 1) {
        if (tid < s) red[tid] = fmaxf(red[tid], red[tid + s]);
        __syncthreads();
    }
    m = red[0];
    __syncthreads();

    float e[8];
    float sum = 0.0f;
#pragma unroll
    for (int u = 0; u < 8; u++) {
        int j = tid + u * 256;
        e[u] = (j < L) ? __expf(v[u] - m) : 0.0f;
        sum += e[u];
    }
    red[tid] = sum;
    __syncthreads();
#pragma unroll
    for (int s = 128; s > 0; s >>= 1) {
        if (tid < s) red[tid] += red[tid + s];
        __syncthreads();
    }
    const float inv = 1.0f / red[0];

#pragma unroll
    for (int u = 0; u < 8; u++) {
        int j = tid + u * 256;
        srow[j] = e[u] * inv;   // j > i gets 0 (e[u]=0)
    }
}

// ---------------------------------------------------------------------------
// Kernel 4: O = P @ V per batch, K-loop truncated at the diagonal row-block.
// grid = (DIM/128, SEQ/128, BATCH)
// ---------------------------------------------------------------------------
__global__ void __launch_bounds__(256) pv_gemm(float* __restrict__ out)
{
    const int bx = blockIdx.x, by = blockIdx.y, b = blockIdx.z;
    const float* A  = g_s + ((size_t)b * SEQ + (size_t)by * 128) * SEQ;
    const float* Bm = g_v + (size_t)b * SEQ * DIM + (size_t)bx * 128;
    float*       C  = out + ((size_t)b * SEQ + (size_t)by * 128) * DIM + (size_t)bx * 128;
    const int kIters = (by + 1) * 128 / 8;   // rows beyond diagonal block are zero
    gemm_body<false>(A, Bm, C, SEQ, DIM, DIM, kIters);
}

// ---------------------------------------------------------------------------
extern "C" void kernel_launch(void* const* d_in, const int* in_sizes, int n_in,
                              void* d_out, int out_size)
{
    const float* x  = (const float*)d_in[0];
    const float* Wq = (const float*)d_in[1];
    const float* Wk = (const float*)d_in[2];
    const float* Wv = (const float*)d_in[3];
    float* out = (float*)d_out;

    dim3 blk(256);
    qkv_gemm<<<dim3(DIM / 128, MTOT / 128, 3), blk>>>(x, Wq, Wk, Wv);
    scores_gemm<<<dim3(SEQ / 128, SEQ / 128, BATCH), blk>>>();
    softmax_causal<<<dim3(MTOT), blk>>>();
    pv_gemm<<<dim3(DIM / 128, SEQ / 128, BATCH), blk>>>(out);
}

// round 2
// speedup vs baseline: 1.7109x; 1.7109x over previous
#include <cuda_runtime.h>
#include <mma.h>

using namespace nvcuda;

#define BATCH 8
#define SEQ   2048
#define DIM   1024
#define MTOT  (BATCH * SEQ)

// Scratch (device bss — no runtime allocation)
__device__ float g_q[(size_t)MTOT * DIM];                 // 64 MB
__device__ float g_k[(size_t)MTOT * DIM];                 // 64 MB
__device__ float g_v[(size_t)MTOT * DIM];                 // 64 MB
__device__ float g_s[(size_t)BATCH * SEQ * SEQ];          // 128 MB

// ---------------------------------------------------------------------------
// cp.async helpers
// ---------------------------------------------------------------------------
__device__ __forceinline__ void cp16(float* dst, const float* src) {
    unsigned sdst = (unsigned)__cvta_generic_to_shared(dst);
    asm volatile("cp.async.cg.shared.global [%0], [%1], 16;" :: "r"(sdst), "l"(src));
}
#define CP_COMMIT()   asm volatile("cp.async.commit_group;")
#define CP_WAIT(N)    asm volatile("cp.async.wait_group %0;" :: "n"(N))

// ---------------------------------------------------------------------------
// 128x128x16 tf32 tensor-core GEMM core. 256 threads = 8 warps (2m x 4n),
// each warp owns a 64x32 tile = 4x2 wmma 16x16x8 fragments, fp32 accumulate.
// A: row-major MxK (tile origin pre-offset).
// B: TRANSB=false -> row-major KxN (origin offset to col tile)
//    TRANSB=true  -> row-major NxK, computes A @ B^T (origin offset to row tile)
// ---------------------------------------------------------------------------
template <bool TRANSB>
__device__ __forceinline__ void gemm_tc(const float* __restrict__ A,
                                        const float* __restrict__ Bm,
                                        float* __restrict__ C,
                                        int lda, int ldb, int ldc, int kIters)
{
    // A tile: 128 rows x 16 k, stride 20 (80B rows -> 16B aligned)
    __shared__ float As[2][128][20];
    // B tile: trans -> 128 n x 16 k (stride 20); non-trans -> 16 k x 128 n (stride 132)
    constexpr int BSR = TRANSB ? 128 : 16;
    constexpr int BSC = TRANSB ? 20  : 132;
    __shared__ float Bs[2][BSR][BSC];

    const int tid = threadIdx.x;
    const int wid = tid >> 5;
    const int wm  = wid >> 2;    // 0..1
    const int wn  = wid & 3;     // 0..3

    wmma::fragment<wmma::accumulator, 16, 16, 8, float> acc[4][2];
#pragma unroll
    for (int i = 0; i < 4; i++)
#pragma unroll
        for (int j = 0; j < 2; j++) wmma::fill_fragment(acc[i][j], 0.0f);

    auto load_tiles = [&](int kt, int buf) {
        // A: 128x16 -> 512 float4, 2 per thread
#pragma unroll
        for (int u = 0; u < 2; u++) {
            int idx = tid + u * 256;
            int row = idx >> 2;
            int c   = (idx & 3) * 4;
            cp16(&As[buf][row][c], A + (size_t)row * lda + kt * 16 + c);
        }
        if (TRANSB) {
#pragma unroll
            for (int u = 0; u < 2; u++) {
                int idx = tid + u * 256;
                int row = idx >> 2;
                int c   = (idx & 3) * 4;
                cp16(&Bs[buf][row][c % BSC], Bm + (size_t)row * ldb + kt * 16 + c);
            }
        } else {
#pragma unroll
            for (int u = 0; u < 2; u++) {
                int idx = tid + u * 256;
                int row = (idx >> 5) % BSR;
                int c   = (idx & 31) * 4;
                cp16(&Bs[buf][row][c], Bm + (size_t)(kt * 16 + row) * ldb + c);
            }
        }
    };

    load_tiles(0, 0);
    CP_COMMIT();

    for (int kt = 0; kt < kIters; kt++) {
        const int cur = kt & 1;
        if (kt + 1 < kIters) {
            load_tiles(kt + 1, cur ^ 1);
            CP_COMMIT();
            CP_WAIT(1);
        } else {
            CP_WAIT(0);
        }
        __syncthreads();

#pragma unroll
        for (int ks = 0; ks < 2; ks++) {
            const int k0 = ks * 8;

            wmma::fragment<wmma::matrix_a, 16, 16, 8, wmma::precision::tf32,
                           wmma::row_major> a[4];
#pragma unroll
            for (int i = 0; i < 4; i++) {
                wmma::load_matrix_sync(a[i], &As[cur][wm * 64 + i * 16][k0], 20);
#pragma unroll
                for (int t = 0; t < a[i].num_elements; t++)
                    a[i].x[t] = wmma::__float_to_tf32(a[i].x[t]);
            }

            if (TRANSB) {
                wmma::fragment<wmma::matrix_b, 16, 16, 8, wmma::precision::tf32,
                               wmma::col_major> b[2];
#pragma unroll
                for (int j = 0; j < 2; j++) {
                    wmma::load_matrix_sync(b[j], &Bs[cur][wn * 32 + j * 16][k0], BSC);
#pragma unroll
                    for (int t = 0; t < b[j].num_elements; t++)
                        b[j].x[t] = wmma::__float_to_tf32(b[j].x[t]);
                }
#pragma unroll
                for (int i = 0; i < 4; i++)
#pragma unroll
                    for (int j = 0; j < 2; j++)
                        wmma::mma_sync(acc[i][j], a[i], b[j], acc[i][j]);
            } else {
                wmma::fragment<wmma::matrix_b, 16, 16, 8, wmma::precision::tf32,
                               wmma::row_major> b[2];
#pragma unroll
                for (int j = 0; j < 2; j++) {
                    wmma::load_matrix_sync(b[j], &Bs[cur][k0][wn * 32 + j * 16], BSC);
#pragma unroll
                    for (int t = 0; t < b[j].num_elements; t++)
                        b[j].x[t] = wmma::__float_to_tf32(b[j].x[t]);
                }
#pragma unroll
                for (int i = 0; i < 4; i++)
#pragma unroll
                    for (int j = 0; j < 2; j++)
                        wmma::mma_sync(acc[i][j], a[i], b[j], acc[i][j]);
            }
        }
        __syncthreads();
    }

#pragma unroll
    for (int i = 0; i < 4; i++)
#pragma unroll
        for (int j = 0; j < 2; j++)
            wmma::store_matrix_sync(C + (size_t)(wm * 64 + i * 16) * ldc +
                                        wn * 32 + j * 16,
                                    acc[i][j], ldc, wmma::mem_row_major);
}

// ---------------------------------------------------------------------------
// Kernel 1: Q/K/V projections. grid = (DIM/128, MTOT/128, 3)
// ---------------------------------------------------------------------------
__global__ void __launch_bounds__(256) qkv_gemm(const float* __restrict__ x,
                                                const float* __restrict__ Wq,
                                                const float* __restrict__ Wk,
                                                const float* __restrict__ Wv)
{
    const float* W   = (blockIdx.z == 0) ? Wq : (blockIdx.z == 1) ? Wk : Wv;
    float*       out = (blockIdx.z == 0) ? g_q : (blockIdx.z == 1) ? g_k : g_v;

    const float* A  = x + (size_t)blockIdx.y * 128 * DIM;
    const float* Bm = W + (size_t)blockIdx.x * 128;
    float*       C  = out + (size_t)blockIdx.y * 128 * DIM + (size_t)blockIdx.x * 128;
    gemm_tc<false>(A, Bm, C, DIM, DIM, DIM, DIM / 16);
}

// ---------------------------------------------------------------------------
// Kernel 2: S = Q @ K^T per batch, skip tiles fully above the causal diagonal.
// grid = (SEQ/128, SEQ/128, BATCH)
// ---------------------------------------------------------------------------
__global__ void __launch_bounds__(256) scores_gemm()
{
    const int bx = blockIdx.x, by = blockIdx.y, b = blockIdx.z;
    if (bx > by) return;  // strictly above diagonal: never read downstream
    const float* A  = g_q + ((size_t)b * SEQ + (size_t)by * 128) * DIM;
    const float* Bm = g_k + ((size_t)b * SEQ + (size_t)bx * 128) * DIM;
    float*       C  = g_s + ((size_t)b * SEQ + (size_t)by * 128) * SEQ + (size_t)bx * 128;
    gemm_tc<true>(A, Bm, C, DIM, DIM, SEQ, DIM / 16);
}

// ---------------------------------------------------------------------------
// Kernel 3: causal softmax over row i (valid length i+1), scale 1/sqrt(1024).
// Writes zeros for j > i so PV can run dense K-tiles through the diagonal.
// ---------------------------------------------------------------------------
__global__ void __launch_bounds__(256) softmax_causal()
{
    __shared__ float red[256];
    const int row = blockIdx.x;
    const int b = row >> 11;           // / SEQ
    const int i = row & (SEQ - 1);
    float* srow = g_s + ((size_t)b * SEQ + i) * SEQ;
    const int L = i + 1;
    const int tid = threadIdx.x;

    float v[8];
    float m = -INFINITY;
#pragma unroll
    for (int u = 0; u < 8; u++) {
        int j = tid + u * 256;
        v[u] = (j < L) ? srow[j] * 0.03125f : -INFINITY;
        m = fmaxf(m, v[u]);
    }
    red[tid] = m;
    __syncthreads();
#pragma unroll
    for (int s = 128; s > 0; s >>= 1) {
        if (tid < s) red[tid] = fmaxf(red[tid], red[tid + s]);
        __syncthreads();
    }
    m = red[0];
    __syncthreads();

    float e[8];
    float sum = 0.0f;
#pragma unroll
    for (int u = 0; u < 8; u++) {
        int j = tid + u * 256;
        e[u] = (j < L) ? __expf(v[u] - m) : 0.0f;
        sum += e[u];
    }
    red[tid] = sum;
    __syncthreads();
#pragma unroll
    for (int s = 128; s > 0; s >>= 1) {
        if (tid < s) red[tid] += red[tid + s];
        __syncthreads();
    }
    const float inv = 1.0f / red[0];

#pragma unroll
    for (int u = 0; u < 8; u++) {
        int j = tid + u * 256;
        srow[j] = e[u] * inv;   // j > i gets 0 (e[u]=0)
    }
}

// ---------------------------------------------------------------------------
// Kernel 4: O = P @ V per batch, K-loop truncated at the diagonal row-block.
// grid = (DIM/128, SEQ/128, BATCH)
// ---------------------------------------------------------------------------
__global__ void __launch_bounds__(256) pv_gemm(float* __restrict__ out)
{
    const int bx = blockIdx.x, by = blockIdx.y, b = blockIdx.z;
    const float* A  = g_s + ((size_t)b * SEQ + (size_t)by * 128) * SEQ;
    const float* Bm = g_v + (size_t)b * SEQ * DIM + (size_t)bx * 128;
    float*       C  = out + ((size_t)b * SEQ + (size_t)by * 128) * DIM + (size_t)bx * 128;
    const int kIters = (by + 1) * 128 / 16;   // rows beyond diagonal block are zero
    gemm_tc<false>(A, Bm, C, SEQ, DIM, DIM, kIters);
}

// ---------------------------------------------------------------------------
extern "C" void kernel_launch(void* const* d_in, const int* in_sizes, int n_in,
                              void* d_out, int out_size)
{
    const float* x  = (const float*)d_in[0];
    const float* Wq = (const float*)d_in[1];
    const float* Wk = (const float*)d_in[2];
    const float* Wv = (const float*)d_in[3];
    float* out = (float*)d_out;

    dim3 blk(256);
    qkv_gemm<<<dim3(DIM / 128, MTOT / 128, 3), blk>>>(x, Wq, Wk, Wv);
    scores_gemm<<<dim3(SEQ / 128, SEQ / 128, BATCH), blk>>>();
    softmax_causal<<<dim3(MTOT), blk>>>();
    pv_gemm<<<dim3(DIM / 128, SEQ / 128, BATCH), blk>>>(out);
}

// round 4
// speedup vs baseline: 1.7207x; 1.0058x over previous
#include <cuda_runtime.h>
#include <mma.h>

using namespace nvcuda;

#define BATCH 8
#define SEQ   2048
#define DIM   1024
#define MTOT  (BATCH * SEQ)

// Scratch (device bss — no runtime allocation)
__device__ float g_q[(size_t)MTOT * DIM];                 // 64 MB (tf32-rounded)
__device__ float g_k[(size_t)MTOT * DIM];                 // 64 MB (tf32-rounded)
__device__ float g_v[(size_t)MTOT * DIM];                 // 64 MB (tf32-rounded)
__device__ float g_s[(size_t)BATCH * SEQ * SEQ];          // 128 MB (probs tf32-rounded)
__device__ float g_xt[(size_t)MTOT * DIM];                // 64 MB (x, tf32-rounded)
__device__ float g_wq[(size_t)DIM * DIM];                 // 4 MB
__device__ float g_wk[(size_t)DIM * DIM];                 // 4 MB
__device__ float g_wv[(size_t)DIM * DIM];                 // 4 MB

// ---------------------------------------------------------------------------
// cp.async helpers
// ---------------------------------------------------------------------------
__device__ __forceinline__ void cp16(float* dst, const float* src) {
    unsigned sdst = (unsigned)__cvta_generic_to_shared(dst);
    asm volatile("cp.async.cg.shared.global [%0], [%1], 16;" :: "r"(sdst), "l"(src));
}
#define CP_COMMIT()   asm volatile("cp.async.commit_group;")
#define CP_WAIT(N)    asm volatile("cp.async.wait_group %0;" :: "n"(N))

// ---------------------------------------------------------------------------
// Kernel 0: round all inputs to tf32-exact, writing to device-scope scratch.
// NOTE: __device__ symbols are referenced ONLY inside device code (passing
// them as kernel args from host is UB — that was the Round 3 bug).
// ---------------------------------------------------------------------------
#define X4   (MTOT * DIM / 4)      // 4M float4
#define W4   (DIM * DIM / 4)       // 256K float4
#define N4TOT (X4 + 3 * W4)

__global__ void __launch_bounds__(256) round_inputs(const float* __restrict__ x,
                                                    const float* __restrict__ Wq,
                                                    const float* __restrict__ Wk,
                                                    const float* __restrict__ Wv)
{
    for (int i = blockIdx.x * blockDim.x + threadIdx.x; i < N4TOT;
         i += gridDim.x * blockDim.x) {
        const float4* src;
        float4* dst;
        if (i < X4) {
            src = (const float4*)x + i;
            dst = (float4*)g_xt + i;
        } else {
            int j = i - X4;
            int which = j / W4;
            int off   = j - which * W4;
            const float* s = (which == 0) ? Wq : (which == 1) ? Wk : Wv;
            float*       d = (which == 0) ? g_wq : (which == 1) ? g_wk : g_wv;
            src = (const float4*)s + off;
            dst = (float4*)d + off;
        }
        float4 v = *src;
        v.x = wmma::__float_to_tf32(v.x);
        v.y = wmma::__float_to_tf32(v.y);
        v.z = wmma::__float_to_tf32(v.z);
        v.w = wmma::__float_to_tf32(v.w);
        *dst = v;
    }
}

// ---------------------------------------------------------------------------
// 128x128x16 tf32 tensor-core GEMM core. 256 threads = 8 warps (2m x 4n),
// each warp owns a 64x32 tile = 4x2 wmma 16x16x8 fragments, fp32 accumulate.
// ALL operands must already be tf32-exact (pre-rounded) — no in-loop converts.
// A: row-major MxK (tile origin pre-offset).
// B: TRANSB=false -> row-major KxN (origin offset to col tile)
//    TRANSB=true  -> row-major NxK, computes A @ B^T (origin offset to row tile)
// ROUND_OUT: tf32-round accumulators before the final store.
// ---------------------------------------------------------------------------
template <bool TRANSB, bool ROUND_OUT>
__device__ __forceinline__ void gemm_tc(const float* __restrict__ A,
                                        const float* __restrict__ Bm,
                                        float* __restrict__ C,
                                        int lda, int ldb, int ldc, int kIters)
{
    __shared__ float As[2][128][20];
    constexpr int BSR = TRANSB ? 128 : 16;
    constexpr int BSC = TRANSB ? 20  : 132;
    __shared__ float Bs[2][BSR][BSC];

    const int tid = threadIdx.x;
    const int wid = tid >> 5;
    const int wm  = wid >> 2;    // 0..1
    const int wn  = wid & 3;     // 0..3

    wmma::fragment<wmma::accumulator, 16, 16, 8, float> acc[4][2];
#pragma unroll
    for (int i = 0; i < 4; i++)
#pragma unroll
        for (int j = 0; j < 2; j++) wmma::fill_fragment(acc[i][j], 0.0f);

    auto load_tiles = [&](int kt, int buf) {
#pragma unroll
        for (int u = 0; u < 2; u++) {
            int idx = tid + u * 256;
            int row = idx >> 2;
            int c   = (idx & 3) * 4;
            cp16(&As[buf][row][c], A + (size_t)row * lda + kt * 16 + c);
        }
        if (TRANSB) {
#pragma unroll
            for (int u = 0; u < 2; u++) {
                int idx = tid + u * 256;
                int row = idx >> 2;
                int c   = (idx & 3) * 4;
                cp16(&Bs[buf][row][c], Bm + (size_t)row * ldb + kt * 16 + c);
            }
        } else {
#pragma unroll
            for (int u = 0; u < 2; u++) {
                int idx = tid + u * 256;
                int row = (idx >> 5) % BSR;
                int c   = (idx & 31) * 4;
                cp16(&Bs[buf][row][c], Bm + (size_t)(kt * 16 + row) * ldb + c);
            }
        }
    };

    load_tiles(0, 0);
    CP_COMMIT();

    for (int kt = 0; kt < kIters; kt++) {
        const int cur = kt & 1;
        if (kt + 1 < kIters) {
            load_tiles(kt + 1, cur ^ 1);
            CP_COMMIT();
            CP_WAIT(1);
        } else {
            CP_WAIT(0);
        }
        __syncthreads();

#pragma unroll
        for (int ks = 0; ks < 2; ks++) {
            const int k0 = ks * 8;

            wmma::fragment<wmma::matrix_a, 16, 16, 8, wmma::precision::tf32,
                           wmma::row_major> a[4];
#pragma unroll
            for (int i = 0; i < 4; i++)
                wmma::load_matrix_sync(a[i], &As[cur][wm * 64 + i * 16][k0], 20);

            if (TRANSB) {
                wmma::fragment<wmma::matrix_b, 16, 16, 8, wmma::precision::tf32,
                               wmma::col_major> b[2];
#pragma unroll
                for (int j = 0; j < 2; j++)
                    wmma::load_matrix_sync(b[j], &Bs[cur][wn * 32 + j * 16][k0], BSC);
#pragma unroll
                for (int i = 0; i < 4; i++)
#pragma unroll
                    for (int j = 0; j < 2; j++)
                        wmma::mma_sync(acc[i][j], a[i], b[j], acc[i][j]);
            } else {
                wmma::fragment<wmma::matrix_b, 16, 16, 8, wmma::precision::tf32,
                               wmma::row_major> b[2];
#pragma unroll
                for (int j = 0; j < 2; j++)
                    wmma::load_matrix_sync(b[j], &Bs[cur][k0][wn * 32 + j * 16], BSC);
#pragma unroll
                for (int i = 0; i < 4; i++)
#pragma unroll
                    for (int j = 0; j < 2; j++)
                        wmma::mma_sync(acc[i][j], a[i], b[j], acc[i][j]);
            }
        }
        __syncthreads();
    }

#pragma unroll
    for (int i = 0; i < 4; i++)
#pragma unroll
        for (int j = 0; j < 2; j++) {
            if (ROUND_OUT) {
#pragma unroll
                for (int t = 0; t < acc[i][j].num_elements; t++)
                    acc[i][j].x[t] = wmma::__float_to_tf32(acc[i][j].x[t]);
            }
            wmma::store_matrix_sync(C + (size_t)(wm * 64 + i * 16) * ldc +
                                        wn * 32 + j * 16,
                                    acc[i][j], ldc, wmma::mem_row_major);
        }
}

// ---------------------------------------------------------------------------
// Kernel 1: Q/K/V projections from pre-rounded x/W. grid=(DIM/128, MTOT/128, 3)
// Outputs tf32-rounded so downstream GEMMs need no conversion.
// ---------------------------------------------------------------------------
__global__ void __launch_bounds__(256) qkv_gemm()
{
    const float* W   = (blockIdx.z == 0) ? g_wq : (blockIdx.z == 1) ? g_wk : g_wv;
    float*       out = (blockIdx.z == 0) ? g_q  : (blockIdx.z == 1) ? g_k  : g_v;

    const float* A  = g_xt + (size_t)blockIdx.y * 128 * DIM;
    const float* Bm = W + (size_t)blockIdx.x * 128;
    float*       C  = out + (size_t)blockIdx.y * 128 * DIM + (size_t)blockIdx.x * 128;
    gemm_tc<false, true>(A, Bm, C, DIM, DIM, DIM, DIM / 16);
}

// ---------------------------------------------------------------------------
// Kernel 2: S = Q @ K^T per batch, skip tiles above the causal diagonal.
// grid = (SEQ/128, SEQ/128, BATCH). Output stays fp32 (consumed by softmax).
// ---------------------------------------------------------------------------
__global__ void __launch_bounds__(256) scores_gemm()
{
    const int bx = blockIdx.x, by = blockIdx.y, b = blockIdx.z;
    if (bx > by) return;
    const float* A  = g_q + ((size_t)b * SEQ + (size_t)by * 128) * DIM;
    const float* Bm = g_k + ((size_t)b * SEQ + (size_t)bx * 128) * DIM;
    float*       C  = g_s + ((size_t)b * SEQ + (size_t)by * 128) * SEQ + (size_t)bx * 128;
    gemm_tc<true, false>(A, Bm, C, DIM, DIM, SEQ, DIM / 16);
}

// ---------------------------------------------------------------------------
// Kernel 3: causal softmax over row i, scale 1/sqrt(1024). Writes tf32-rounded
// probabilities, zeros for j > i so PV runs dense through the diagonal block.
// ---------------------------------------------------------------------------
__global__ void __launch_bounds__(256) softmax_causal()
{
    __shared__ float red[256];
    const int row = blockIdx.x;
    const int b = row >> 11;
    const int i = row & (SEQ - 1);
    float* srow = g_s + ((size_t)b * SEQ + i) * SEQ;
    const int L = i + 1;
    const int tid = threadIdx.x;

    float v[8];
    float m = -INFINITY;
#pragma unroll
    for (int u = 0; u < 8; u++) {
        int j = tid + u * 256;
        v[u] = (j < L) ? srow[j] * 0.03125f : -INFINITY;
        m = fmaxf(m, v[u]);
    }
    red[tid] = m;
    __syncthreads();
#pragma unroll
    for (int s = 128; s > 0; s >>= 1) {
        if (tid < s) red[tid] = fmaxf(red[tid], red[tid + s]);
        __syncthreads();
    }
    m = red[0];
    __syncthreads();

    float e[8];
    float sum = 0.0f;
#pragma unroll
    for (int u = 0; u < 8; u++) {
        int j = tid + u * 256;
        e[u] = (j < L) ? __expf(v[u] - m) : 0.0f;
        sum += e[u];
    }
    red[tid] = sum;
    __syncthreads();
#pragma unroll
    for (int s = 128; s > 0; s >>= 1) {
        if (tid < s) red[tid] += red[tid + s];
        __syncthreads();
    }
    const float inv = 1.0f / red[0];

#pragma unroll
    for (int u = 0; u < 8; u++) {
        int j = tid + u * 256;
        srow[j] = wmma::__float_to_tf32(e[u] * inv);   // j > i gets 0
    }
}

// ---------------------------------------------------------------------------
// Kernel 4: O = P @ V per batch, K-loop truncated at the diagonal row-block.
// grid = (DIM/128, SEQ/128, BATCH). Output fp32 (final).
// ---------------------------------------------------------------------------
__global__ void __launch_bounds__(256) pv_gemm(float* __restrict__ out)
{
    const int bx = blockIdx.x, by = blockIdx.y, b = blockIdx.z;
    const float* A  = g_s + ((size_t)b * SEQ + (size_t)by * 128) * SEQ;
    const float* Bm = g_v + (size_t)b * SEQ * DIM + (size_t)bx * 128;
    float*       C  = out + ((size_t)b * SEQ + (size_t)by * 128) * DIM + (size_t)bx * 128;
    const int kIters = (by + 1) * 128 / 16;
    gemm_tc<false, false>(A, Bm, C, SEQ, DIM, DIM, kIters);
}

// ---------------------------------------------------------------------------
extern "C" void kernel_launch(void* const* d_in, const int* in_sizes, int n_in,
                              void* d_out, int out_size)
{
    const float* x  = (const float*)d_in[0];
    const float* Wq = (const float*)d_in[1];
    const float* Wk = (const float*)d_in[2];
    const float* Wv = (const float*)d_in[3];
    float* out = (float*)d_out;

    dim3 blk(256);
    round_inputs<<<2048, blk>>>(x, Wq, Wk, Wv);
    qkv_gemm<<<dim3(DIM / 128, MTOT / 128, 3), blk>>>();
    scores_gemm<<<dim3(SEQ / 128, SEQ / 128, BATCH), blk>>>();
    softmax_causal<<<dim3(MTOT), blk>>>();
    pv_gemm<<<dim3(DIM / 128, SEQ / 128, BATCH), blk>>>(out);
}

// round 6
// speedup vs baseline: 1.8720x; 1.0879x over previous
#include <cuda_runtime.h>
#include <mma.h>

using namespace nvcuda;

#define BATCH 8
#define SEQ   2048
#define DIM   1024
#define MTOT  (BATCH * SEQ)

// ---------------------------------------------------------------------------
// Device scratch (bss — no runtime allocation)
// ---------------------------------------------------------------------------
__device__ float g_q  [(size_t)MTOT * DIM];        // tf32-rounded
__device__ float g_k  [(size_t)MTOT * DIM];        // tf32-rounded
__device__ float g_v  [(size_t)MTOT * DIM];        // tf32-rounded
__device__ float g_vt [(size_t)MTOT * DIM];        // V^T per batch [DIM][SEQ]
__device__ float g_s  [(size_t)BATCH * SEQ * SEQ]; // scores/probs
__device__ float g_xt [(size_t)MTOT * DIM];        // x tf32-rounded
__device__ float g_wqT[(size_t)DIM * DIM];         // W^T [DOUT][DIN] tf32-rounded
__device__ float g_wkT[(size_t)DIM * DIM];
__device__ float g_wvT[(size_t)DIM * DIM];

// ---------------------------------------------------------------------------
// cp.async helpers
// ---------------------------------------------------------------------------
__device__ __forceinline__ void cp16(float* dst, const float* src) {
    unsigned sdst = (unsigned)__cvta_generic_to_shared(dst);
    asm volatile("cp.async.cg.shared.global [%0], [%1], 16;" :: "r"(sdst), "l"(src));
}
#define CP_COMMIT() asm volatile("cp.async.commit_group;")

// ---------------------------------------------------------------------------
// Unified GEMM: C[128,128] = A[128,K] @ B[128,K]^T, both K-major row-major.
// 128 threads = 4 warps in 2x2; each warp owns a 64x64 tile = 4x4 wmma
// 16x16x8 tf32 fragments (fp32 accumulate).
// Per-K16: frag LDS ~16KB vs 16KB cp.async stores vs 256 HMMA cycles
// -> tensor-limited (R2 config was smem-limited at 48KB/K16).
// ---------------------------------------------------------------------------
template <bool ROUND_OUT>
__device__ __forceinline__ void gemm_body(const float* __restrict__ A,
                                          const float* __restrict__ B,
                                          float* __restrict__ C,
                                          int lda, int ldb, int ldc, int kIters)
{
    __shared__ float As[2][128][20];
    __shared__ float Bs[2][128][20];

    const int tid = threadIdx.x;          // 0..127
    const int wid = tid >> 5;             // 0..3
    const int wm  = wid >> 1;             // 0..1
    const int wn  = wid & 1;              // 0..1

    wmma::fragment<wmma::accumulator, 16, 16, 8, float> acc[4][4];
#pragma unroll
    for (int i = 0; i < 4; i++)
#pragma unroll
        for (int j = 0; j < 4; j++) wmma::fill_fragment(acc[i][j], 0.0f);

    auto load_tiles = [&](int kt, int buf) {
#pragma unroll
        for (int u = 0; u < 4; u++) {
            int idx = u * 128 + tid;      // 0..511
            int row = idx >> 2;           // 0..127
            int c   = (idx & 3) * 4;      // 0,4,8,12
            cp16(&As[buf][row][c], A + (size_t)row * lda + kt * 16 + c);
            cp16(&Bs[buf][row][c], B + (size_t)row * ldb + kt * 16 + c);
        }
        CP_COMMIT();
    };

    load_tiles(0, 0);

    for (int kt = 0; kt < kIters; kt++) {
        const int cur = kt & 1;
        if (kt + 1 < kIters) {
            load_tiles(kt + 1, cur ^ 1);
            asm volatile("cp.async.wait_group 1;");
        } else {
            asm volatile("cp.async.wait_group 0;");
        }
        __syncthreads();

#pragma unroll
        for (int ks = 0; ks < 2; ks++) {
            const int k0 = ks * 8;

            wmma::fragment<wmma::matrix_a, 16, 16, 8, wmma::precision::tf32,
                           wmma::row_major> a[4];
            wmma::fragment<wmma::matrix_b, 16, 16, 8, wmma::precision::tf32,
                           wmma::col_major> b[4];
#pragma unroll
            for (int i = 0; i < 4; i++)
                wmma::load_matrix_sync(a[i], &As[cur][wm * 64 + i * 16][k0], 20);
#pragma unroll
            for (int j = 0; j < 4; j++)
                wmma::load_matrix_sync(b[j], &Bs[cur][wn * 64 + j * 16][k0], 20);
#pragma unroll
            for (int i = 0; i < 4; i++)
#pragma unroll
                for (int j = 0; j < 4; j++)
                    wmma::mma_sync(acc[i][j], a[i], b[j], acc[i][j]);
        }
        __syncthreads();
    }

#pragma unroll
    for (int i = 0; i < 4; i++)
#pragma unroll
        for (int j = 0; j < 4; j++) {
            if (ROUND_OUT) {
#pragma unroll
                for (int t = 0; t < acc[i][j].num_elements; t++)
                    acc[i][j].x[t] = wmma::__float_to_tf32(acc[i][j].x[t]);
            }
            wmma::store_matrix_sync(C + (size_t)(wm * 64 + i * 16) * ldc +
                                        wn * 64 + j * 16,
                                    acc[i][j], ldc, wmma::mem_row_major);
        }
}

// ---------------------------------------------------------------------------
// GEMM kernels (all: C = A[M][K] * B[N][K]^T)
// ---------------------------------------------------------------------------
__global__ void __launch_bounds__(128) qkv_gemm()
{
    const float* W   = (blockIdx.z == 0) ? g_wqT : (blockIdx.z == 1) ? g_wkT : g_wvT;
    float*       out = (blockIdx.z == 0) ? g_q   : (blockIdx.z == 1) ? g_k   : g_v;
    const float* A = g_xt + (size_t)blockIdx.y * 128 * DIM;
    const float* B = W    + (size_t)blockIdx.x * 128 * DIM;
    float*       C = out  + (size_t)blockIdx.y * 128 * DIM + (size_t)blockIdx.x * 128;
    gemm_body<true>(A, B, C, DIM, DIM, DIM, DIM / 16);
}

__global__ void __launch_bounds__(128) scores_gemm()
{
    const int bx = blockIdx.x, by = blockIdx.y, b = blockIdx.z;
    if (bx > by) return;   // strictly above causal diagonal: never read
    const float* A = g_q + ((size_t)b * SEQ + (size_t)by * 128) * DIM;
    const float* B = g_k + ((size_t)b * SEQ + (size_t)bx * 128) * DIM;
    float*       C = g_s + ((size_t)b * SEQ + (size_t)by * 128) * SEQ + (size_t)bx * 128;
    gemm_body<false>(A, B, C, DIM, DIM, SEQ, DIM / 16);
}

__global__ void __launch_bounds__(128) pv_gemm(float* __restrict__ out)
{
    const int bx = blockIdx.x, by = blockIdx.y, b = blockIdx.z;
    const float* A = g_s  + ((size_t)b * SEQ + (size_t)by * 128) * SEQ;
    const float* B = g_vt + (size_t)b * DIM * SEQ + (size_t)bx * 128 * SEQ;
    float*       C = out  + ((size_t)b * SEQ + (size_t)by * 128) * DIM + (size_t)bx * 128;
    gemm_body<false>(A, B, C, SEQ, SEQ, DIM, (by + 1) * 8);  // K truncated at diag
}

// ---------------------------------------------------------------------------
// Data prep
// ---------------------------------------------------------------------------
__global__ void __launch_bounds__(256) round_x(const float* __restrict__ x)
{
    const int N4 = MTOT * DIM / 4;
    for (int i = blockIdx.x * blockDim.x + threadIdx.x; i < N4;
         i += gridDim.x * blockDim.x) {
        float4 v = ((const float4*)x)[i];
        v.x = wmma::__float_to_tf32(v.x);
        v.y = wmma::__float_to_tf32(v.y);
        v.z = wmma::__float_to_tf32(v.z);
        v.w = wmma::__float_to_tf32(v.w);
        ((float4*)g_xt)[i] = v;
    }
}

// W [DIN][DOUT] -> W^T [DOUT][DIN], tf32-rounded. grid (32,32,3), block (32,8)
__global__ void wT_round(const float* __restrict__ Wq,
                         const float* __restrict__ Wk,
                         const float* __restrict__ Wv)
{
    __shared__ float t[32][33];
    const float* in  = (blockIdx.z == 0) ? Wq : (blockIdx.z == 1) ? Wk : Wv;
    float*       out = (blockIdx.z == 0) ? g_wqT : (blockIdx.z == 1) ? g_wkT : g_wvT;
    const int n0 = blockIdx.x * 32, k0 = blockIdx.y * 32;
    const int tx = threadIdx.x, ty = threadIdx.y;
#pragma unroll
    for (int i = 0; i < 32; i += 8)
        t[ty + i][tx] = wmma::__float_to_tf32(in[(size_t)(k0 + ty + i) * DIM + n0 + tx]);
    __syncthreads();
#pragma unroll
    for (int i = 0; i < 32; i += 8)
        out[(size_t)(n0 + ty + i) * DIM + k0 + tx] = t[tx][ty + i];
}

// V [b][SEQ][DIM] -> V^T [b][DIM][SEQ]. grid (DIM/32, SEQ/32, 8), block (32,8)
__global__ void vT_kernel()
{
    __shared__ float t[32][33];
    const int b = blockIdx.z;
    const float* in  = g_v  + (size_t)b * SEQ * DIM;
    float*       out = g_vt + (size_t)b * DIM * SEQ;
    const int n0 = blockIdx.x * 32, k0 = blockIdx.y * 32;
    const int tx = threadIdx.x, ty = threadIdx.y;
#pragma unroll
    for (int i = 0; i < 32; i += 8)
        t[ty + i][tx] = in[(size_t)(k0 + ty + i) * DIM + n0 + tx];
    __syncthreads();
#pragma unroll
    for (int i = 0; i < 32; i += 8)
        out[(size_t)(n0 + ty + i) * SEQ + k0 + tx] = t[tx][ty + i];
}

// ---------------------------------------------------------------------------
// Causal softmax (writes tf32-rounded probs, zeros above diagonal)
// ---------------------------------------------------------------------------
__global__ void __launch_bounds__(256) softmax_causal()
{
    __shared__ float red[256];
    const int row = blockIdx.x;
    const int b = row >> 11;
    const int i = row & (SEQ - 1);
    float* srow = g_s + ((size_t)b * SEQ + i) * SEQ;
    const int L = i + 1;
    const int tid = threadIdx.x;

    float v[8];
    float m = -INFINITY;
#pragma unroll
    for (int u = 0; u < 8; u++) {
        int j = tid + u * 256;
        v[u] = (j < L) ? srow[j] * 0.03125f : -INFINITY;
        m = fmaxf(m, v[u]);
    }
    red[tid] = m;
    __syncthreads();
#pragma unroll
    for (int s = 128; s > 0; s >>= 1) {
        if (tid < s) red[tid] = fmaxf(red[tid], red[tid + s]);
        __syncthreads();
    }
    m = red[0];
    __syncthreads();

    float e[8];
    float sum = 0.0f;
#pragma unroll
    for (int u = 0; u < 8; u++) {
        int j = tid + u * 256;
        e[u] = (j < L) ? __expf(v[u] - m) : 0.0f;
        sum += e[u];
    }
    red[tid] = sum;
    __syncthreads();
#pragma unroll
    for (int s = 128; s > 0; s >>= 1) {
        if (tid < s) red[tid] += red[tid + s];
        __syncthreads();
    }
    const float inv = 1.0f / red[0];

#pragma unroll
    for (int u = 0; u < 8; u++) {
        int j = tid + u * 256;
        srow[j] = wmma::__float_to_tf32(e[u] * inv);
    }
}

// ---------------------------------------------------------------------------
extern "C" void kernel_launch(void* const* d_in, const int* in_sizes, int n_in,
                              void* d_out, int out_size)
{
    const float* x  = (const float*)d_in[0];
    const float* Wq = (const float*)d_in[1];
    const float* Wk = (const float*)d_in[2];
    const float* Wv = (const float*)d_in[3];
    float* out = (float*)d_out;

    dim3 gblk(128);
    dim3 tblk(32, 8);

    round_x<<<2048, 256>>>(x);
    wT_round<<<dim3(32, 32, 3), tblk>>>(Wq, Wk, Wv);
    qkv_gemm<<<dim3(DIM / 128, MTOT / 128, 3), gblk>>>();
    vT_kernel<<<dim3(DIM / 32, SEQ / 32, BATCH), tblk>>>();
    scores_gemm<<<dim3(SEQ / 128, SEQ / 128, BATCH), gblk>>>();
    softmax_causal<<<dim3(MTOT), 256>>>();
    pv_gemm<<<dim3(DIM / 128, SEQ / 128, BATCH), gblk>>>(out);
}

// round 7
// speedup vs baseline: 6.4576x; 3.4496x over previous
#include <cuda_runtime.h>
#include <cuda_fp16.h>
#include <mma.h>

using namespace nvcuda;

#define BATCH 8
#define SEQ   2048
#define DIM   1024
#define MTOT  (BATCH * SEQ)

// ---------------------------------------------------------------------------
// Device scratch (bss — no runtime allocation)
// ---------------------------------------------------------------------------
__device__ __half g_xh [(size_t)MTOT * DIM];        // x (fp16)
__device__ __half g_qh [(size_t)MTOT * DIM];        // Q (fp16)
__device__ __half g_kh [(size_t)MTOT * DIM];        // K (fp16)
__device__ __half g_vh [(size_t)MTOT * DIM];        // V (fp16, natural)
__device__ __half g_vth[(size_t)MTOT * DIM];        // V^T per batch [DIM][SEQ]
__device__ float  g_s  [(size_t)BATCH * SEQ * SEQ]; // scores (fp32)
__device__ __half g_p  [(size_t)BATCH * SEQ * SEQ]; // probs (fp16)
__device__ __half g_wqT[(size_t)DIM * DIM];         // W^T [DOUT][DIN] fp16
__device__ __half g_wkT[(size_t)DIM * DIM];
__device__ __half g_wvT[(size_t)DIM * DIM];

// ---------------------------------------------------------------------------
// cp.async helper (16B)
// ---------------------------------------------------------------------------
__device__ __forceinline__ void cp16(void* dst, const void* src) {
    unsigned sdst = (unsigned)__cvta_generic_to_shared(dst);
    asm volatile("cp.async.cg.shared.global [%0], [%1], 16;" :: "r"(sdst), "l"(src));
}
#define CP_COMMIT() asm volatile("cp.async.commit_group;")

// ---------------------------------------------------------------------------
// Unified fp16 GEMM: C[128,128] = A[128,K] @ B[128,K]^T, K-major half inputs,
// fp32 accumulate. 128 threads = 4 warps (2x2), 64x64 per warp = 4x4
// m16n16k16 fragments. K consumed in chunks of 32, double buffered.
// SMEM: one 40KB pool (tiles during mainloop, fp32 staging in epilogue).
// OUT_HALF: convert accumulators to fp16 via staged epilogue; else direct
// fp32 store_matrix_sync.
// ---------------------------------------------------------------------------
#define BK       32
#define TSTRIDE  40            // halves per tile row (80B, 16B-aligned)
#define TILE_H   (128 * TSTRIDE)   // halves per tile buffer

template <bool OUT_HALF>
__device__ __forceinline__ void gemm_body(const __half* __restrict__ A,
                                          const __half* __restrict__ B,
                                          void* __restrict__ Cout,
                                          int lda, int ldb, int ldc, int kIters)
{
    __shared__ __align__(16) unsigned char smem_raw[2 * 2 * TILE_H * 2]; // 40960B

    __half* Ah = (__half*)smem_raw;            // [2][128][TSTRIDE]
    __half* Bh = Ah + 2 * TILE_H;              // [2][128][TSTRIDE]

    const int tid = threadIdx.x;               // 0..127
    const int wid = tid >> 5;
    const int wm  = wid >> 1;                  // 0..1
    const int wn  = wid & 1;                   // 0..1

    wmma::fragment<wmma::accumulator, 16, 16, 16, float> acc[4][4];
#pragma unroll
    for (int i = 0; i < 4; i++)
#pragma unroll
        for (int j = 0; j < 4; j++) wmma::fill_fragment(acc[i][j], 0.0f);

    auto load_tiles = [&](int kt, int buf) {
        __half* Ad = Ah + buf * TILE_H;
        __half* Bd = Bh + buf * TILE_H;
#pragma unroll
        for (int u = 0; u < 4; u++) {
            int idx = u * 128 + tid;           // 0..511
            int row = idx >> 2;                // 0..127
            int c8  = (idx & 3) * 8;           // half offset 0,8,16,24
            cp16(Ad + row * TSTRIDE + c8, A + (size_t)row * lda + kt * BK + c8);
            cp16(Bd + row * TSTRIDE + c8, B + (size_t)row * ldb + kt * BK + c8);
        }
        CP_COMMIT();
    };

    load_tiles(0, 0);

    for (int kt = 0; kt < kIters; kt++) {
        const int cur = kt & 1;
        if (kt + 1 < kIters) {
            load_tiles(kt + 1, cur ^ 1);
            asm volatile("cp.async.wait_group 1;");
        } else {
            asm volatile("cp.async.wait_group 0;");
        }
        __syncthreads();

        const __half* At = Ah + cur * TILE_H;
        const __half* Bt = Bh + cur * TILE_H;
#pragma unroll
        for (int ks = 0; ks < 2; ks++) {
            const int k0 = ks * 16;

            wmma::fragment<wmma::matrix_a, 16, 16, 16, __half, wmma::row_major> a[4];
            wmma::fragment<wmma::matrix_b, 16, 16, 16, __half, wmma::col_major> b[4];
#pragma unroll
            for (int i = 0; i < 4; i++)
                wmma::load_matrix_sync(a[i], At + (wm * 64 + i * 16) * TSTRIDE + k0, TSTRIDE);
#pragma unroll
            for (int j = 0; j < 4; j++)
                wmma::load_matrix_sync(b[j], Bt + (wn * 64 + j * 16) * TSTRIDE + k0, TSTRIDE);
#pragma unroll
            for (int i = 0; i < 4; i++)
#pragma unroll
                for (int j = 0; j < 4; j++)
                    wmma::mma_sync(acc[i][j], a[i], b[j], acc[i][j]);
        }
        __syncthreads();
    }

    if (OUT_HALF) {
        // Stage fp32 accs in SMEM (pool is free now), convert to half, write.
        __half* Ch = (__half*)Cout;
        float* st = ((float*)smem_raw) + wid * 1024;  // 64x16 per warp
        const int lane = tid & 31;
#pragma unroll
        for (int j = 0; j < 4; j++) {
#pragma unroll
            for (int i = 0; i < 4; i++)
                wmma::store_matrix_sync(st + i * 256, acc[i][j], 16, wmma::mem_row_major);
            __syncwarp();
#pragma unroll
            for (int t = 0; t < 16; t++) {
                int idx = lane + t * 32;   // 0..511 half2 units
                int row = idx >> 3;        // 0..63
                int c2  = idx & 7;
                __half2 h = __floats2half2_rn(st[row * 16 + c2 * 2],
                                              st[row * 16 + c2 * 2 + 1]);
                *(__half2*)(Ch + (size_t)(wm * 64 + row) * ldc +
                            wn * 64 + j * 16 + c2 * 2) = h;
            }
            __syncwarp();
        }
    } else {
        float* Cf = (float*)Cout;
#pragma unroll
        for (int i = 0; i < 4; i++)
#pragma unroll
            for (int j = 0; j < 4; j++)
                wmma::store_matrix_sync(Cf + (size_t)(wm * 64 + i * 16) * ldc +
                                            wn * 64 + j * 16,
                                        acc[i][j], ldc, wmma::mem_row_major);
    }
}

// ---------------------------------------------------------------------------
// GEMM kernels (all: C = A[M][K] * B[N][K]^T)
// ---------------------------------------------------------------------------
__global__ void __launch_bounds__(128) qkv_gemm()
{
    const __half* W   = (blockIdx.z == 0) ? g_wqT : (blockIdx.z == 1) ? g_wkT : g_wvT;
    __half*       out = (blockIdx.z == 0) ? g_qh  : (blockIdx.z == 1) ? g_kh  : g_vh;
    const __half* A = g_xh + (size_t)blockIdx.y * 128 * DIM;
    const __half* B = W    + (size_t)blockIdx.x * 128 * DIM;
    __half*       C = out  + (size_t)blockIdx.y * 128 * DIM + (size_t)blockIdx.x * 128;
    gemm_body<true>(A, B, C, DIM, DIM, DIM, DIM / BK);
}

__global__ void __launch_bounds__(128) scores_gemm()
{
    const int bx = blockIdx.x, by = blockIdx.y, b = blockIdx.z;
    if (bx > by) return;   // strictly above causal diagonal: never read
    const __half* A = g_qh + ((size_t)b * SEQ + (size_t)by * 128) * DIM;
    const __half* B = g_kh + ((size_t)b * SEQ + (size_t)bx * 128) * DIM;
    float*        C = g_s  + ((size_t)b * SEQ + (size_t)by * 128) * SEQ + (size_t)bx * 128;
    gemm_body<false>(A, B, C, DIM, DIM, SEQ, DIM / BK);
}

__global__ void __launch_bounds__(128) pv_gemm(float* __restrict__ out)
{
    const int bx = blockIdx.x, by = blockIdx.y, b = blockIdx.z;
    const __half* A = g_p   + ((size_t)b * SEQ + (size_t)by * 128) * SEQ;
    const __half* B = g_vth + (size_t)b * DIM * SEQ + (size_t)bx * 128 * SEQ;
    float*        C = out   + ((size_t)b * SEQ + (size_t)by * 128) * DIM + (size_t)bx * 128;
    gemm_body<false>(A, B, C, SEQ, SEQ, DIM, (by + 1) * (128 / BK));  // K to diag
}

// ---------------------------------------------------------------------------
// Data prep
// ---------------------------------------------------------------------------
__global__ void __launch_bounds__(256) x_to_half(const float* __restrict__ x)
{
    const int N4 = MTOT * DIM / 4;
    for (int i = blockIdx.x * blockDim.x + threadIdx.x; i < N4;
         i += gridDim.x * blockDim.x) {
        float4 v = ((const float4*)x)[i];
        __half2* dst = (__half2*)g_xh + 2 * i;
        dst[0] = __floats2half2_rn(v.x, v.y);
        dst[1] = __floats2half2_rn(v.z, v.w);
    }
}

// W [DIN][DOUT] -> W^T [DOUT][DIN] fp16. grid (32,32,3), block (32,8)
__global__ void wT_half(const float* __restrict__ Wq,
                        const float* __restrict__ Wk,
                        const float* __restrict__ Wv)
{
    __shared__ float t[32][33];
    const float* in   = (blockIdx.z == 0) ? Wq : (blockIdx.z == 1) ? Wk : Wv;
    __half*      out  = (blockIdx.z == 0) ? g_wqT : (blockIdx.z == 1) ? g_wkT : g_wvT;
    const int n0 = blockIdx.x * 32, k0 = blockIdx.y * 32;
    const int tx = threadIdx.x, ty = threadIdx.y;
#pragma unroll
    for (int i = 0; i < 32; i += 8)
        t[ty + i][tx] = in[(size_t)(k0 + ty + i) * DIM + n0 + tx];
    __syncthreads();
#pragma unroll
    for (int i = 0; i < 32; i += 8)
        out[(size_t)(n0 + ty + i) * DIM + k0 + tx] = __float2half_rn(t[tx][ty + i]);
}

// V [b][SEQ][DIM] -> V^T [b][DIM][SEQ] fp16. grid (DIM/32, SEQ/32, 8), block (32,8)
__global__ void vT_half()
{
    __shared__ __half t[32][34];
    const int b = blockIdx.z;
    const __half* in  = g_vh  + (size_t)b * SEQ * DIM;
    __half*       out = g_vth + (size_t)b * DIM * SEQ;
    const int n0 = blockIdx.x * 32, k0 = blockIdx.y * 32;
    const int tx = threadIdx.x, ty = threadIdx.y;
#pragma unroll
    for (int i = 0; i < 32; i += 8)
        t[ty + i][tx] = in[(size_t)(k0 + ty + i) * DIM + n0 + tx];
    __syncthreads();
#pragma unroll
    for (int i = 0; i < 32; i += 8)
        out[(size_t)(n0 + ty + i) * SEQ + k0 + tx] = t[tx][ty + i];
}

// ---------------------------------------------------------------------------
// Causal softmax: fp32 scores in, fp16 probs out (zeros above diagonal).
// ---------------------------------------------------------------------------
__global__ void __launch_bounds__(256) softmax_causal()
{
    __shared__ float red[256];
    const int row = blockIdx.x;
    const int b = row >> 11;
    const int i = row & (SEQ - 1);
    const float* srow = g_s + ((size_t)b * SEQ + i) * SEQ;
    __half*      prow = g_p + ((size_t)b * SEQ + i) * SEQ;
    const int L = i + 1;
    const int tid = threadIdx.x;

    float v[8];
    float m = -INFINITY;
#pragma unroll
    for (int u = 0; u < 8; u++) {
        int j = tid + u * 256;
        v[u] = (j < L) ? srow[j] * 0.03125f : -INFINITY;
        m = fmaxf(m, v[u]);
    }
    red[tid] = m;
    __syncthreads();
#pragma unroll
    for (int s = 128; s > 0; s >>= 1) {
        if (tid < s) red[tid] = fmaxf(red[tid], red[tid + s]);
        __syncthreads();
    }
    m = red[0];
    __syncthreads();

    float e[8];
    float sum = 0.0f;
#pragma unroll
    for (int u = 0; u < 8; u++) {
        int j = tid + u * 256;
        e[u] = (j < L) ? __expf(v[u] - m) : 0.0f;
        sum += e[u];
    }
    red[tid] = sum;
    __syncthreads();
#pragma unroll
    for (int s = 128; s > 0; s >>= 1) {
        if (tid < s) red[tid] += red[tid + s];
        __syncthreads();
    }
    const float inv = 1.0f / red[0];

#pragma unroll
    for (int u = 0; u < 8; u++) {
        int j = tid + u * 256;
        prow[j] = __float2half_rn(e[u] * inv);   // j > i gets 0
    }
}

// ---------------------------------------------------------------------------
extern "C" void kernel_launch(void* const* d_in, const int* in_sizes, int n_in,
                              void* d_out, int out_size)
{
    const float* x  = (const float*)d_in[0];
    const float* Wq = (const float*)d_in[1];
    const float* Wk = (const float*)d_in[2];
    const float* Wv = (const float*)d_in[3];
    float* out = (float*)d_out;

    dim3 gblk(128);
    dim3 tblk(32, 8);

    x_to_half<<<2048, 256>>>(x);
    wT_half<<<dim3(32, 32, 3), tblk>>>(Wq, Wk, Wv);
    qkv_gemm<<<dim3(DIM / 128, MTOT / 128, 3), gblk>>>();
    vT_half<<<dim3(DIM / 32, SEQ / 32, BATCH), tblk>>>();
    scores_gemm<<<dim3(SEQ / 128, SEQ / 128, BATCH), gblk>>>();
    softmax_causal<<<dim3(MTOT), 256>>>();
    pv_gemm<<<dim3(DIM / 128, SEQ / 128, BATCH), gblk>>>(out);
}

// round 8
// speedup vs baseline: 6.5324x; 1.0116x over previous
#include <cuda_runtime.h>
#include <cuda_fp16.h>
#include <mma.h>

using namespace nvcuda;

#define BATCH 8
#define SEQ   2048
#define DIM   1024
#define MTOT  (BATCH * SEQ)

// ---------------------------------------------------------------------------
// Device scratch (bss — no runtime allocation)
// ---------------------------------------------------------------------------
__device__ __half g_xh [(size_t)MTOT * DIM];        // x (fp16)
__device__ __half g_qh [(size_t)MTOT * DIM];        // Q (fp16)
__device__ __half g_kh [(size_t)MTOT * DIM];        // K (fp16)
__device__ __half g_vth[(size_t)MTOT * DIM];        // V^T per batch [DIM][SEQ]
__device__ float  g_s  [(size_t)BATCH * SEQ * SEQ]; // scores (fp32)
__device__ __half g_p  [(size_t)BATCH * SEQ * SEQ]; // probs (fp16)
__device__ __half g_wqT[(size_t)DIM * DIM];         // W^T [DOUT][DIN] fp16
__device__ __half g_wkT[(size_t)DIM * DIM];
__device__ __half g_wvT[(size_t)DIM * DIM];

// ---------------------------------------------------------------------------
// cp.async helper (16B)
// ---------------------------------------------------------------------------
__device__ __forceinline__ void cp16(void* dst, const void* src) {
    unsigned sdst = (unsigned)__cvta_generic_to_shared(dst);
    asm volatile("cp.async.cg.shared.global [%0], [%1], 16;" :: "r"(sdst), "l"(src));
}
#define CP_COMMIT() asm volatile("cp.async.commit_group;")

// ---------------------------------------------------------------------------
// Unified fp16 GEMM: C[128,128] = A[128,K] @ B[128,K]^T, fp32 accumulate.
// 128 threads = 4 warps (2x2), 64x64 per warp = 4x4 m16n16k16 fragments.
// 3-stage cp.async pipeline over BK=32 chunks. Dynamic SMEM 61440B.
// OUT_MODE: 0 = fp32 direct, 1 = fp16 (staged convert), 2 = fp16 transposed
// (staged via mem_col_major; used to emit V^T straight from the QKV GEMM).
// ---------------------------------------------------------------------------
#define BK        32
#define TSTRIDE   40                 // halves per tile row (80B, 16B-aligned)
#define CHUNK_H   (128 * TSTRIDE)    // halves per tile buffer (10240B)
#define SMEM_DYN  (3 * 2 * CHUNK_H * 2)  // 61440B

template <int OUT_MODE>
__device__ __forceinline__ void gemm_body(const __half* __restrict__ A,
                                          const __half* __restrict__ B,
                                          void* __restrict__ Cout,
                                          int lda, int ldb, int ldc, int kIters)
{
    extern __shared__ __align__(16) unsigned char dynraw[];
    __half* pool = (__half*)dynraw;

    const int tid = threadIdx.x;               // 0..127
    const int wid = tid >> 5;
    const int lane = tid & 31;
    const int wm  = wid >> 1;                  // 0..1
    const int wn  = wid & 1;                   // 0..1

    wmma::fragment<wmma::accumulator, 16, 16, 16, float> acc[4][4];
#pragma unroll
    for (int i = 0; i < 4; i++)
#pragma unroll
        for (int j = 0; j < 4; j++) wmma::fill_fragment(acc[i][j], 0.0f);

    auto load_chunk = [&](int kt, int stage) {
        __half* Ad = pool + stage * 2 * CHUNK_H;
        __half* Bd = Ad + CHUNK_H;
#pragma unroll
        for (int u = 0; u < 4; u++) {
            int idx = u * 128 + tid;           // 0..511
            int row = idx >> 2;                // 0..127
            int c8  = (idx & 3) * 8;           // half offset 0,8,16,24
            cp16(Ad + row * TSTRIDE + c8, A + (size_t)row * lda + kt * BK + c8);
            cp16(Bd + row * TSTRIDE + c8, B + (size_t)row * ldb + kt * BK + c8);
        }
        CP_COMMIT();
    };

    load_chunk(0, 0);
    if (kIters > 1) load_chunk(1, 1);

    for (int kt = 0; kt < kIters; kt++) {
        const int cur = kt % 3;
        if (kt + 2 < kIters) {
            load_chunk(kt + 2, (kt + 2) % 3);
            asm volatile("cp.async.wait_group 2;");
        } else if (kt + 1 < kIters) {
            asm volatile("cp.async.wait_group 1;");
        } else {
            asm volatile("cp.async.wait_group 0;");
        }
        __syncthreads();

        const __half* At = pool + cur * 2 * CHUNK_H;
        const __half* Bt = At + CHUNK_H;
#pragma unroll
        for (int ks = 0; ks < 2; ks++) {
            const int k0 = ks * 16;

            wmma::fragment<wmma::matrix_a, 16, 16, 16, __half, wmma::row_major> a[4];
            wmma::fragment<wmma::matrix_b, 16, 16, 16, __half, wmma::col_major> b[4];
#pragma unroll
            for (int i = 0; i < 4; i++)
                wmma::load_matrix_sync(a[i], At + (wm * 64 + i * 16) * TSTRIDE + k0, TSTRIDE);
#pragma unroll
            for (int j = 0; j < 4; j++)
                wmma::load_matrix_sync(b[j], Bt + (wn * 64 + j * 16) * TSTRIDE + k0, TSTRIDE);
#pragma unroll
            for (int i = 0; i < 4; i++)
#pragma unroll
                for (int j = 0; j < 4; j++)
                    wmma::mma_sync(acc[i][j], a[i], b[j], acc[i][j]);
        }
        __syncthreads();
    }

    if (OUT_MODE == 0) {
        float* Cf = (float*)Cout;
#pragma unroll
        for (int i = 0; i < 4; i++)
#pragma unroll
            for (int j = 0; j < 4; j++)
                wmma::store_matrix_sync(Cf + (size_t)(wm * 64 + i * 16) * ldc +
                                            wn * 64 + j * 16,
                                        acc[i][j], ldc, wmma::mem_row_major);
    } else if (OUT_MODE == 1) {
        // fp16 output: stage fp32 accs in SMEM (pool free now), convert, write.
        __half* Ch = (__half*)Cout;
        float* st = ((float*)pool) + wid * 1024;   // 64x16 per warp
#pragma unroll
        for (int j = 0; j < 4; j++) {
#pragma unroll
            for (int i = 0; i < 4; i++)
                wmma::store_matrix_sync(st + i * 256, acc[i][j], 16, wmma::mem_row_major);
            __syncwarp();
#pragma unroll
            for (int t = 0; t < 16; t++) {
                int idx = lane + t * 32;   // 0..511 half2 units
                int row = idx >> 3;        // 0..63
                int c2  = idx & 7;
                __half2 h = __floats2half2_rn(st[row * 16 + c2 * 2],
                                              st[row * 16 + c2 * 2 + 1]);
                *(__half2*)(Ch + (size_t)(wm * 64 + row) * ldc +
                            wn * 64 + j * 16 + c2 * 2) = h;
            }
            __syncwarp();
        }
    } else {
        // Transposed fp16 output (V^T): acc tile is [seq=16][dim=16]; stage
        // col-major so staging is [dim][seq], then write half2 along seq.
        // Cout points at vt tile base; ldc = stride of the dim dimension (SEQ).
        __half* Ch = (__half*)Cout;
        float* st = ((float*)pool) + wid * 288;    // 16x17 per warp
#pragma unroll
        for (int i = 0; i < 4; i++) {
#pragma unroll
            for (int j = 0; j < 4; j++) {
                wmma::store_matrix_sync(st, acc[i][j], 17, wmma::mem_col_major);
                __syncwarp();
#pragma unroll
                for (int t = 0; t < 4; t++) {
                    int u  = lane + t * 32;   // 0..127 half2 units
                    int d  = u >> 3;          // 0..15 (dim)
                    int s2 = u & 7;           // seq pair
                    __half2 h = __floats2half2_rn(st[d * 17 + s2 * 2],
                                                  st[d * 17 + s2 * 2 + 1]);
                    *(__half2*)(Ch + (size_t)(wn * 64 + j * 16 + d) * ldc +
                                wm * 64 + i * 16 + s2 * 2) = h;
                }
                __syncwarp();
            }
        }
    }
}

// ---------------------------------------------------------------------------
// GEMM kernels (all: C = A[M][K] * B[N][K]^T)
// ---------------------------------------------------------------------------
__global__ void __launch_bounds__(128) qkv_gemm()
{
    const int z = blockIdx.z;
    const __half* W = (z == 0) ? g_wqT : (z == 1) ? g_wkT : g_wvT;
    const __half* A = g_xh + (size_t)blockIdx.y * 128 * DIM;
    const __half* B = W    + (size_t)blockIdx.x * 128 * DIM;

    if (z == 2) {
        // V: write transposed into g_vth[batch][DIM][SEQ]
        const int batch = blockIdx.y >> 4;            // SEQ/128 = 16 blocks/batch
        const int seq0  = (blockIdx.y & 15) * 128;
        __half* C = g_vth + (size_t)batch * DIM * SEQ +
                    (size_t)blockIdx.x * 128 * SEQ + seq0;
        gemm_body<2>(A, B, C, DIM, DIM, SEQ, DIM / BK);
    } else {
        __half* out = (z == 0) ? g_qh : g_kh;
        __half* C = out + (size_t)blockIdx.y * 128 * DIM + (size_t)blockIdx.x * 128;
        gemm_body<1>(A, B, C, DIM, DIM, DIM, DIM / BK);
    }
}

__global__ void __launch_bounds__(128) scores_gemm()
{
    const int bx = blockIdx.x, by = blockIdx.y, b = blockIdx.z;
    if (bx > by) return;   // strictly above causal diagonal: never read
    const __half* A = g_qh + ((size_t)b * SEQ + (size_t)by * 128) * DIM;
    const __half* B = g_kh + ((size_t)b * SEQ + (size_t)bx * 128) * DIM;
    float*        C = g_s  + ((size_t)b * SEQ + (size_t)by * 128) * SEQ + (size_t)bx * 128;
    gemm_body<0>(A, B, C, DIM, DIM, SEQ, DIM / BK);
}

__global__ void __launch_bounds__(128) pv_gemm(float* __restrict__ out)
{
    const int bx = blockIdx.x, by = blockIdx.y, b = blockIdx.z;
    const __half* A = g_p   + ((size_t)b * SEQ + (size_t)by * 128) * SEQ;
    const __half* B = g_vth + (size_t)b * DIM * SEQ + (size_t)bx * 128 * SEQ;
    float*        C = out   + ((size_t)b * SEQ + (size_t)by * 128) * DIM + (size_t)bx * 128;
    gemm_body<0>(A, B, C, SEQ, SEQ, DIM, (by + 1) * (128 / BK));  // K to diag
}

// ---------------------------------------------------------------------------
// Data prep
// ---------------------------------------------------------------------------
__global__ void __launch_bounds__(256) x_to_half(const float* __restrict__ x)
{
    const int N4 = MTOT * DIM / 4;
    for (int i = blockIdx.x * blockDim.x + threadIdx.x; i < N4;
         i += gridDim.x * blockDim.x) {
        float4 v = ((const float4*)x)[i];
        __half2* dst = (__half2*)g_xh + 2 * i;
        dst[0] = __floats2half2_rn(v.x, v.y);
        dst[1] = __floats2half2_rn(v.z, v.w);
    }
}

// W [DIN][DOUT] -> W^T [DOUT][DIN] fp16. grid (32,32,3), block (32,8)
__global__ void wT_half(const float* __restrict__ Wq,
                        const float* __restrict__ Wk,
                        const float* __restrict__ Wv)
{
    __shared__ float t[32][33];
    const float* in   = (blockIdx.z == 0) ? Wq : (blockIdx.z == 1) ? Wk : Wv;
    __half*      out  = (blockIdx.z == 0) ? g_wqT : (blockIdx.z == 1) ? g_wkT : g_wvT;
    const int n0 = blockIdx.x * 32, k0 = blockIdx.y * 32;
    const int tx = threadIdx.x, ty = threadIdx.y;
#pragma unroll
    for (int i = 0; i < 32; i += 8)
        t[ty + i][tx] = in[(size_t)(k0 + ty + i) * DIM + n0 + tx];
    __syncthreads();
#pragma unroll
    for (int i = 0; i < 32; i += 8)
        out[(size_t)(n0 + ty + i) * DIM + k0 + tx] = __float2half_rn(t[tx][ty + i]);
}

// ---------------------------------------------------------------------------
// Causal softmax: fp32 scores in, fp16 probs out. Only writes the columns PV
// will read: [0, ceil(L/128)*128) — zeros fill the diagonal block's tail.
// ---------------------------------------------------------------------------
__global__ void __launch_bounds__(256) softmax_causal()
{
    __shared__ float red[256];
    const int row = blockIdx.x;
    const int b = row >> 11;
    const int i = row & (SEQ - 1);
    const float* srow = g_s + ((size_t)b * SEQ + i) * SEQ;
    __half*      prow = g_p + ((size_t)b * SEQ + i) * SEQ;
    const int L = i + 1;
    const int Lpad = (L + 127) & ~127;
    const int tid = threadIdx.x;

    float v[8];
    float m = -INFINITY;
#pragma unroll
    for (int u = 0; u < 8; u++) {
        int j = tid + u * 256;
        v[u] = (j < L) ? srow[j] * 0.03125f : -INFINITY;
        m = fmaxf(m, v[u]);
    }
    red[tid] = m;
    __syncthreads();
#pragma unroll
    for (int s = 128; s > 0; s >>= 1) {
        if (tid < s) red[tid] = fmaxf(red[tid], red[tid + s]);
        __syncthreads();
    }
    m = red[0];
    __syncthreads();

    float e[8];
    float sum = 0.0f;
#pragma unroll
    for (int u = 0; u < 8; u++) {
        int j = tid + u * 256;
        e[u] = (j < L) ? __expf(v[u] - m) : 0.0f;
        sum += e[u];
    }
    red[tid] = sum;
    __syncthreads();
#pragma unroll
    for (int s = 128; s > 0; s >>= 1) {
        if (tid < s) red[tid] += red[tid + s];
        __syncthreads();
    }
    const float inv = 1.0f / red[0];

#pragma unroll
    for (int u = 0; u < 8; u++) {
        int j = tid + u * 256;
        if (j < Lpad) prow[j] = __float2half_rn(e[u] * inv);   // j >= L -> 0
    }
}

// ---------------------------------------------------------------------------
extern "C" void kernel_launch(void* const* d_in, const int* in_sizes, int n_in,
                              void* d_out, int out_size)
{
    const float* x  = (const float*)d_in[0];
    const float* Wq = (const float*)d_in[1];
    const float* Wk = (const float*)d_in[2];
    const float* Wv = (const float*)d_in[3];
    float* out = (float*)d_out;

    cudaFuncSetAttribute(qkv_gemm,    cudaFuncAttributeMaxDynamicSharedMemorySize, SMEM_DYN);
    cudaFuncSetAttribute(scores_gemm, cudaFuncAttributeMaxDynamicSharedMemorySize, SMEM_DYN);
    cudaFuncSetAttribute(pv_gemm,     cudaFuncAttributeMaxDynamicSharedMemorySize, SMEM_DYN);

    dim3 gblk(128);
    dim3 tblk(32, 8);

    x_to_half<<<2048, 256>>>(x);
    wT_half<<<dim3(32, 32, 3), tblk>>>(Wq, Wk, Wv);
    qkv_gemm<<<dim3(DIM / 128, MTOT / 128, 3), gblk, SMEM_DYN>>>();
    scores_gemm<<<dim3(SEQ / 128, SEQ / 128, BATCH), gblk, SMEM_DYN>>>();  // 4th: profiled
    softmax_causal<<<dim3(MTOT), 256>>>();
    pv_gemm<<<dim3(DIM / 128, SEQ / 128, BATCH), gblk, SMEM_DYN>>>(out);
}

// round 9
// speedup vs baseline: 6.7240x; 1.0293x over previous
#include <cuda_runtime.h>
#include <cuda_fp16.h>
#include <mma.h>

using namespace nvcuda;

#define BATCH 8
#define SEQ   2048
#define DIM   1024
#define MTOT  (BATCH * SEQ)

// ---------------------------------------------------------------------------
// Device scratch (bss — no runtime allocation)
// ---------------------------------------------------------------------------
__device__ __half g_xh [(size_t)MTOT * DIM];        // x (fp16)
__device__ __half g_qh [(size_t)MTOT * DIM];        // Q (fp16)
__device__ __half g_kh [(size_t)MTOT * DIM];        // K (fp16)
__device__ __half g_vth[(size_t)MTOT * DIM];        // V^T per batch [DIM][SEQ]
__device__ float  g_s  [(size_t)BATCH * SEQ * SEQ]; // scores (fp32)
__device__ __half g_p  [(size_t)BATCH * SEQ * SEQ]; // probs (fp16)
__device__ __half g_wqT[(size_t)DIM * DIM];         // W^T [DOUT][DIN] fp16
__device__ __half g_wkT[(size_t)DIM * DIM];
__device__ __half g_wvT[(size_t)DIM * DIM];

// ---------------------------------------------------------------------------
// cp.async helper (16B)
// ---------------------------------------------------------------------------
__device__ __forceinline__ void cp16(void* dst, const void* src) {
    unsigned sdst = (unsigned)__cvta_generic_to_shared(dst);
    asm volatile("cp.async.cg.shared.global [%0], [%1], 16;" :: "r"(sdst), "l"(src));
}
#define CP_COMMIT() asm volatile("cp.async.commit_group;")

// ---------------------------------------------------------------------------
// fp16 GEMM: C[128,128] = A[128,K] @ B[128,K]^T, fp32 accumulate.
// 256 threads = 8 warps (2m x 4n); warp tile 64x32 = 4x2 m16n16k16 frags
// (64 acc regs -> ~120 total -> 2 CTAs/SM = 16 warps, vs 12 in R8).
// BK=64 chunks, 2-stage cp.async pipeline. Dynamic SMEM 73728B.
// OUT_MODE: 0 = fp32 direct, 1 = fp16 (staged convert), 2 = fp16 transposed
// (staged mem_col_major; emits V^T straight from the QKV GEMM).
// ---------------------------------------------------------------------------
#define BK        64
#define TSTRIDE   72                  // halves per tile row (144B, 16B-aligned)
#define CHUNK_H   (128 * TSTRIDE)     // halves per tile (18432B)
#define SMEM_DYN  (2 * 2 * CHUNK_H * 2)   // 73728B

template <int OUT_MODE>
__device__ __forceinline__ void gemm_body(const __half* __restrict__ A,
                                          const __half* __restrict__ B,
                                          void* __restrict__ Cout,
                                          int lda, int ldb, int ldc, int kIters)
{
    extern __shared__ __align__(16) unsigned char dynraw[];
    __half* pool = (__half*)dynraw;

    const int tid  = threadIdx.x;               // 0..255
    const int wid  = tid >> 5;                  // 0..7
    const int lane = tid & 31;
    const int wm   = wid >> 2;                  // 0..1  (64-row slab)
    const int wn   = wid & 3;                   // 0..3  (32-col slab)

    wmma::fragment<wmma::accumulator, 16, 16, 16, float> acc[4][2];
#pragma unroll
    for (int i = 0; i < 4; i++)
#pragma unroll
        for (int j = 0; j < 2; j++) wmma::fill_fragment(acc[i][j], 0.0f);

    auto load_chunk = [&](int kt, int stage) {
        __half* Ad = pool + stage * 2 * CHUNK_H;
        __half* Bd = Ad + CHUNK_H;
#pragma unroll
        for (int u = 0; u < 4; u++) {
            int idx = u * 256 + tid;            // 0..1023
            int row = idx >> 3;                 // 0..127
            int c8  = (idx & 7) * 8;            // half offset 0..56
            cp16(Ad + row * TSTRIDE + c8, A + (size_t)row * lda + kt * BK + c8);
            cp16(Bd + row * TSTRIDE + c8, B + (size_t)row * ldb + kt * BK + c8);
        }
        CP_COMMIT();
    };

    load_chunk(0, 0);
    if (kIters > 1) load_chunk(1, 1);

    for (int kt = 0; kt < kIters; kt++) {
        const int cur = kt & 1;
        if (kt + 1 < kIters) asm volatile("cp.async.wait_group 1;");
        else                 asm volatile("cp.async.wait_group 0;");
        __syncthreads();

        const __half* At = pool + cur * 2 * CHUNK_H;
        const __half* Bt = At + CHUNK_H;
#pragma unroll
        for (int ks = 0; ks < 4; ks++) {
            const int k0 = ks * 16;

            wmma::fragment<wmma::matrix_a, 16, 16, 16, __half, wmma::row_major> a[4];
            wmma::fragment<wmma::matrix_b, 16, 16, 16, __half, wmma::col_major> b[2];
#pragma unroll
            for (int i = 0; i < 4; i++)
                wmma::load_matrix_sync(a[i], At + (wm * 64 + i * 16) * TSTRIDE + k0, TSTRIDE);
#pragma unroll
            for (int j = 0; j < 2; j++)
                wmma::load_matrix_sync(b[j], Bt + (wn * 32 + j * 16) * TSTRIDE + k0, TSTRIDE);
#pragma unroll
            for (int i = 0; i < 4; i++)
#pragma unroll
                for (int j = 0; j < 2; j++)
                    wmma::mma_sync(acc[i][j], a[i], b[j], acc[i][j]);
        }
        __syncthreads();
        if (kt + 2 < kIters) load_chunk(kt + 2, cur);
    }

    if (OUT_MODE == 0) {
        float* Cf = (float*)Cout;
#pragma unroll
        for (int i = 0; i < 4; i++)
#pragma unroll
            for (int j = 0; j < 2; j++)
                wmma::store_matrix_sync(Cf + (size_t)(wm * 64 + i * 16) * ldc +
                                            wn * 32 + j * 16,
                                        acc[i][j], ldc, wmma::mem_row_major);
    } else if (OUT_MODE == 1) {
        // fp16 output: stage 64x32 fp32 per warp in SMEM, convert, write half2.
        __half* Ch = (__half*)Cout;
        float* st = ((float*)pool) + wid * 2048;    // 64x32 fp32 = 8KB/warp
#pragma unroll
        for (int i = 0; i < 4; i++)
#pragma unroll
            for (int j = 0; j < 2; j++)
                wmma::store_matrix_sync(st + (i * 16) * 32 + j * 16, acc[i][j],
                                        32, wmma::mem_row_major);
        __syncwarp();
#pragma unroll
        for (int t = 0; t < 32; t++) {
            int idx = lane + t * 32;    // 0..1023 half2 units
            int row = idx >> 4;         // 0..63
            int c2  = idx & 15;         // half2 col
            __half2 h = __floats2half2_rn(st[row * 32 + c2 * 2],
                                          st[row * 32 + c2 * 2 + 1]);
            *(__half2*)(Ch + (size_t)(wm * 64 + row) * ldc +
                        wn * 32 + c2 * 2) = h;
        }
    } else {
        // Transposed fp16 output (V^T): stage col-major per fragment.
        __half* Ch = (__half*)Cout;
        float* st = ((float*)pool) + wid * 288;     // 16x17 fp32 per warp
#pragma unroll
        for (int i = 0; i < 4; i++) {
#pragma unroll
            for (int j = 0; j < 2; j++) {
                wmma::store_matrix_sync(st, acc[i][j], 17, wmma::mem_col_major);
                __syncwarp();
#pragma unroll
                for (int t = 0; t < 4; t++) {
                    int u  = lane + t * 32;   // 0..127 half2 units
                    int d  = u >> 3;          // 0..15 (dim)
                    int s2 = u & 7;           // seq pair
                    __half2 h = __floats2half2_rn(st[d * 17 + s2 * 2],
                                                  st[d * 17 + s2 * 2 + 1]);
                    *(__half2*)(Ch + (size_t)(wn * 32 + j * 16 + d) * ldc +
                                wm * 64 + i * 16 + s2 * 2) = h;
                }
                __syncwarp();
            }
        }
    }
}

// ---------------------------------------------------------------------------
// GEMM kernels (all: C = A[M][K] * B[N][K]^T)
// ---------------------------------------------------------------------------
__global__ void __launch_bounds__(256, 2) qkv_gemm()
{
    const int z = blockIdx.z;
    const __half* W = (z == 0) ? g_wqT : (z == 1) ? g_wkT : g_wvT;
    const __half* A = g_xh + (size_t)blockIdx.y * 128 * DIM;
    const __half* B = W    + (size_t)blockIdx.x * 128 * DIM;

    if (z == 2) {
        // V: write transposed into g_vth[batch][DIM][SEQ]
        const int batch = blockIdx.y >> 4;            // SEQ/128 = 16 blocks/batch
        const int seq0  = (blockIdx.y & 15) * 128;
        __half* C = g_vth + (size_t)batch * DIM * SEQ +
                    (size_t)blockIdx.x * 128 * SEQ + seq0;
        gemm_body<2>(A, B, C, DIM, DIM, SEQ, DIM / BK);
    } else {
        __half* out = (z == 0) ? g_qh : g_kh;
        __half* C = out + (size_t)blockIdx.y * 128 * DIM + (size_t)blockIdx.x * 128;
        gemm_body<1>(A, B, C, DIM, DIM, DIM, DIM / BK);
    }
}

__global__ void __launch_bounds__(256, 2) scores_gemm()
{
    const int bx = blockIdx.x, by = blockIdx.y, b = blockIdx.z;
    if (bx > by) return;   // strictly above causal diagonal: never read
    const __half* A = g_qh + ((size_t)b * SEQ + (size_t)by * 128) * DIM;
    const __half* B = g_kh + ((size_t)b * SEQ + (size_t)bx * 128) * DIM;
    float*        C = g_s  + ((size_t)b * SEQ + (size_t)by * 128) * SEQ + (size_t)bx * 128;
    gemm_body<0>(A, B, C, DIM, DIM, SEQ, DIM / BK);
}

__global__ void __launch_bounds__(256, 2) pv_gemm(float* __restrict__ out)
{
    const int bx = blockIdx.x, by = blockIdx.y, b = blockIdx.z;
    const __half* A = g_p   + ((size_t)b * SEQ + (size_t)by * 128) * SEQ;
    const __half* B = g_vth + (size_t)b * DIM * SEQ + (size_t)bx * 128 * SEQ;
    float*        C = out   + ((size_t)b * SEQ + (size_t)by * 128) * DIM + (size_t)bx * 128;
    gemm_body<0>(A, B, C, SEQ, SEQ, DIM, (by + 1) * (128 / BK));  // K to diag
}

// ---------------------------------------------------------------------------
// Data prep
// ---------------------------------------------------------------------------
__global__ void __launch_bounds__(256) x_to_half(const float* __restrict__ x)
{
    const int N4 = MTOT * DIM / 4;
    for (int i = blockIdx.x * blockDim.x + threadIdx.x; i < N4;
         i += gridDim.x * blockDim.x) {
        float4 v = ((const float4*)x)[i];
        __half2* dst = (__half2*)g_xh + 2 * i;
        dst[0] = __floats2half2_rn(v.x, v.y);
        dst[1] = __floats2half2_rn(v.z, v.w);
    }
}

// W [DIN][DOUT] -> W^T [DOUT][DIN] fp16. grid (32,32,3), block (32,8)
__global__ void wT_half(const float* __restrict__ Wq,
                        const float* __restrict__ Wk,
                        const float* __restrict__ Wv)
{
    __shared__ float t[32][33];
    const float* in   = (blockIdx.z == 0) ? Wq : (blockIdx.z == 1) ? Wk : Wv;
    __half*      out  = (blockIdx.z == 0) ? g_wqT : (blockIdx.z == 1) ? g_wkT : g_wvT;
    const int n0 = blockIdx.x * 32, k0 = blockIdx.y * 32;
    const int tx = threadIdx.x, ty = threadIdx.y;
#pragma unroll
    for (int i = 0; i < 32; i += 8)
        t[ty + i][tx] = in[(size_t)(k0 + ty + i) * DIM + n0 + tx];
    __syncthreads();
#pragma unroll
    for (int i = 0; i < 32; i += 8)
        out[(size_t)(n0 + ty + i) * DIM + k0 + tx] = __float2half_rn(t[tx][ty + i]);
}

// ---------------------------------------------------------------------------
// Causal softmax: fp32 scores in, fp16 probs out. Writes only the columns PV
// reads: [0, ceil(L/128)*128).
// ---------------------------------------------------------------------------
__global__ void __launch_bounds__(256) softmax_causal()
{
    __shared__ float red[256];
    const int row = blockIdx.x;
    const int b = row >> 11;
    const int i = row & (SEQ - 1);
    const float* srow = g_s + ((size_t)b * SEQ + i) * SEQ;
    __half*      prow = g_p + ((size_t)b * SEQ + i) * SEQ;
    const int L = i + 1;
    const int Lpad = (L + 127) & ~127;
    const int tid = threadIdx.x;

    float v[8];
    float m = -INFINITY;
#pragma unroll
    for (int u = 0; u < 8; u++) {
        int j = tid + u * 256;
        v[u] = (j < L) ? srow[j] * 0.03125f : -INFINITY;
        m = fmaxf(m, v[u]);
    }
    red[tid] = m;
    __syncthreads();
#pragma unroll
    for (int s = 128; s > 0; s >>= 1) {
        if (tid < s) red[tid] = fmaxf(red[tid], red[tid + s]);
        __syncthreads();
    }
    m = red[0];
    __syncthreads();

    float e[8];
    float sum = 0.0f;
#pragma unroll
    for (int u = 0; u < 8; u++) {
        int j = tid + u * 256;
        e[u] = (j < L) ? __expf(v[u] - m) : 0.0f;
        sum += e[u];
    }
    red[tid] = sum;
    __syncthreads();
#pragma unroll
    for (int s = 128; s > 0; s >>= 1) {
        if (tid < s) red[tid] += red[tid + s];
        __syncthreads();
    }
    const float inv = 1.0f / red[0];

#pragma unroll
    for (int u = 0; u < 8; u++) {
        int j = tid + u * 256;
        if (j < Lpad) prow[j] = __float2half_rn(e[u] * inv);   // j >= L -> 0
    }
}

// ---------------------------------------------------------------------------
extern "C" void kernel_launch(void* const* d_in, const int* in_sizes, int n_in,
                              void* d_out, int out_size)
{
    const float* x  = (const float*)d_in[0];
    const float* Wq = (const float*)d_in[1];
    const float* Wk = (const float*)d_in[2];
    const float* Wv = (const float*)d_in[3];
    float* out = (float*)d_out;

    cudaFuncSetAttribute(qkv_gemm,    cudaFuncAttributeMaxDynamicSharedMemorySize, SMEM_DYN);
    cudaFuncSetAttribute(scores_gemm, cudaFuncAttributeMaxDynamicSharedMemorySize, SMEM_DYN);
    cudaFuncSetAttribute(pv_gemm,     cudaFuncAttributeMaxDynamicSharedMemorySize, SMEM_DYN);

    dim3 gblk(256);
    dim3 tblk(32, 8);

    x_to_half<<<2048, 256>>>(x);
    wT_half<<<dim3(32, 32, 3), tblk>>>(Wq, Wk, Wv);
    qkv_gemm<<<dim3(DIM / 128, MTOT / 128, 3), gblk, SMEM_DYN>>>();
    scores_gemm<<<dim3(SEQ / 128, SEQ / 128, BATCH), gblk, SMEM_DYN>>>();
    softmax_causal<<<dim3(MTOT), 256>>>();
    pv_gemm<<<dim3(DIM / 128, SEQ / 128, BATCH), gblk, SMEM_DYN>>>(out);
}

// round 10
// speedup vs baseline: 6.9778x; 1.0377x over previous
#include <cuda_runtime.h>
#include <cuda_fp16.h>
#include <mma.h>

using namespace nvcuda;

#define BATCH 8
#define SEQ   2048
#define DIM   1024
#define MTOT  (BATCH * SEQ)

// ---------------------------------------------------------------------------
// Device scratch (bss — no runtime allocation)
// ---------------------------------------------------------------------------
__device__ __half g_xh [(size_t)MTOT * DIM];        // x (fp16)
__device__ __half g_qh [(size_t)MTOT * DIM];        // Q (fp16)
__device__ __half g_kh [(size_t)MTOT * DIM];        // K (fp16)
__device__ __half g_vth[(size_t)MTOT * DIM];        // V^T per batch [DIM][SEQ]
__device__ float  g_s  [(size_t)BATCH * SEQ * SEQ]; // scores (fp32)
__device__ __half g_p  [(size_t)BATCH * SEQ * SEQ]; // probs (fp16)
__device__ __half g_wqT[(size_t)DIM * DIM];         // W^T [DOUT][DIN] fp16
__device__ __half g_wkT[(size_t)DIM * DIM];
__device__ __half g_wvT[(size_t)DIM * DIM];

// ---------------------------------------------------------------------------
// cp.async helper (16B)
// ---------------------------------------------------------------------------
__device__ __forceinline__ void cp16(void* dst, const void* src) {
    unsigned sdst = (unsigned)__cvta_generic_to_shared(dst);
    asm volatile("cp.async.cg.shared.global [%0], [%1], 16;" :: "r"(sdst), "l"(src));
}
#define CP_COMMIT() asm volatile("cp.async.commit_group;")

// ---------------------------------------------------------------------------
// fp16 GEMM: C[128,128] = A[128,K] @ B[128,K]^T, fp32 accumulate.
// 256 threads = 8 warps (2m x 4n); warp tile 64x32 = 4x2 m16n16k16 frags.
// BK=64 chunks, 3-stage cp.async pipeline, ONE __syncthreads per iteration
// (stage (kt-1)%3 being overwritten was consumed before the barrier all
// warps already passed -> second barrier provably unnecessary).
// Dynamic SMEM 110592B; 2 CTAs/SM = 221KB fits the 228KB carveout.
// OUT_MODE: 0 = fp32 direct, 1 = fp16 (staged convert), 2 = fp16 transposed.
// ---------------------------------------------------------------------------
#define BK        64
#define TSTRIDE   72                    // halves per tile row (144B)
#define CHUNK_H   (128 * TSTRIDE)       // halves per matrix chunk (18432B)
#define STAGE_H   (2 * CHUNK_H)         // A+B per stage
#define SMEM_DYN  (3 * STAGE_H * 2)     // 110592B

template <int OUT_MODE>
__device__ __forceinline__ void gemm_body(const __half* __restrict__ A,
                                          const __half* __restrict__ B,
                                          void* __restrict__ Cout,
                                          int lda, int ldb, int ldc, int kIters)
{
    extern __shared__ __align__(16) unsigned char dynraw[];
    __half* pool = (__half*)dynraw;

    const int tid  = threadIdx.x;               // 0..255
    const int wid  = tid >> 5;                  // 0..7
    const int lane = tid & 31;
    const int wm   = wid >> 2;                  // 0..1  (64-row slab)
    const int wn   = wid & 3;                   // 0..3  (32-col slab)

    wmma::fragment<wmma::accumulator, 16, 16, 16, float> acc[4][2];
#pragma unroll
    for (int i = 0; i < 4; i++)
#pragma unroll
        for (int j = 0; j < 2; j++) wmma::fill_fragment(acc[i][j], 0.0f);

    auto load_chunk = [&](int kt) {
        __half* Ad = pool + (kt % 3) * STAGE_H;
        __half* Bd = Ad + CHUNK_H;
#pragma unroll
        for (int u = 0; u < 4; u++) {
            int idx = u * 256 + tid;            // 0..1023
            int row = idx >> 3;                 // 0..127
            int c8  = (idx & 7) * 8;            // half offset 0..56
            cp16(Ad + row * TSTRIDE + c8, A + (size_t)row * lda + kt * BK + c8);
            cp16(Bd + row * TSTRIDE + c8, B + (size_t)row * ldb + kt * BK + c8);
        }
        CP_COMMIT();
    };

    load_chunk(0);
    if (kIters > 1) load_chunk(1);

    for (int kt = 0; kt < kIters; kt++) {
        if (kt + 1 < kIters) asm volatile("cp.async.wait_group 1;");
        else                 asm volatile("cp.async.wait_group 0;");
        __syncthreads();
        if (kt + 2 < kIters) load_chunk(kt + 2);   // writes stage (kt-1)%3: free

        const __half* At = pool + (kt % 3) * STAGE_H;
        const __half* Bt = At + CHUNK_H;
#pragma unroll
        for (int ks = 0; ks < 4; ks++) {
            const int k0 = ks * 16;

            wmma::fragment<wmma::matrix_a, 16, 16, 16, __half, wmma::row_major> a[4];
            wmma::fragment<wmma::matrix_b, 16, 16, 16, __half, wmma::col_major> b[2];
#pragma unroll
            for (int i = 0; i < 4; i++)
                wmma::load_matrix_sync(a[i], At + (wm * 64 + i * 16) * TSTRIDE + k0, TSTRIDE);
#pragma unroll
            for (int j = 0; j < 2; j++)
                wmma::load_matrix_sync(b[j], Bt + (wn * 32 + j * 16) * TSTRIDE + k0, TSTRIDE);
#pragma unroll
            for (int i = 0; i < 4; i++)
#pragma unroll
                for (int j = 0; j < 2; j++)
                    wmma::mma_sync(acc[i][j], a[i], b[j], acc[i][j]);
        }
    }

    if (OUT_MODE == 0) {
        float* Cf = (float*)Cout;
#pragma unroll
        for (int i = 0; i < 4; i++)
#pragma unroll
            for (int j = 0; j < 2; j++)
                wmma::store_matrix_sync(Cf + (size_t)(wm * 64 + i * 16) * ldc +
                                            wn * 32 + j * 16,
                                        acc[i][j], ldc, wmma::mem_row_major);
    } else if (OUT_MODE == 1) {
        // fp16 output: stage 64x32 fp32 per warp in SMEM, convert, write half2.
        __syncthreads();   // pool reuse: all warps done with final stage
        __half* Ch = (__half*)Cout;
        float* st = ((float*)pool) + wid * 2048;    // 64x32 fp32 = 8KB/warp
#pragma unroll
        for (int i = 0; i < 4; i++)
#pragma unroll
            for (int j = 0; j < 2; j++)
                wmma::store_matrix_sync(st + (i * 16) * 32 + j * 16, acc[i][j],
                                        32, wmma::mem_row_major);
        __syncwarp();
#pragma unroll
        for (int t = 0; t < 32; t++) {
            int idx = lane + t * 32;    // 0..1023 half2 units
            int row = idx >> 4;         // 0..63
            int c2  = idx & 15;         // half2 col
            __half2 h = __floats2half2_rn(st[row * 32 + c2 * 2],
                                          st[row * 32 + c2 * 2 + 1]);
            *(__half2*)(Ch + (size_t)(wm * 64 + row) * ldc +
                        wn * 32 + c2 * 2) = h;
        }
    } else {
        // Transposed fp16 output (V^T): stage col-major per fragment.
        __syncthreads();   // pool reuse
        __half* Ch = (__half*)Cout;
        float* st = ((float*)pool) + wid * 288;     // 16x17 fp32 per warp
#pragma unroll
        for (int i = 0; i < 4; i++) {
#pragma unroll
            for (int j = 0; j < 2; j++) {
                wmma::store_matrix_sync(st, acc[i][j], 17, wmma::mem_col_major);
                __syncwarp();
#pragma unroll
                for (int t = 0; t < 4; t++) {
                    int u  = lane + t * 32;   // 0..127 half2 units
                    int d  = u >> 3;          // 0..15 (dim)
                    int s2 = u & 7;           // seq pair
                    __half2 h = __floats2half2_rn(st[d * 17 + s2 * 2],
                                                  st[d * 17 + s2 * 2 + 1]);
                    *(__half2*)(Ch + (size_t)(wn * 32 + j * 16 + d) * ldc +
                                wm * 64 + i * 16 + s2 * 2) = h;
                }
                __syncwarp();
            }
        }
    }
}

// ---------------------------------------------------------------------------
// GEMM kernels (all: C = A[M][K] * B[N][K]^T)
// ---------------------------------------------------------------------------
__global__ void __launch_bounds__(256, 2) qkv_gemm()
{
    const int z = blockIdx.z;
    const __half* W = (z == 0) ? g_wqT : (z == 1) ? g_wkT : g_wvT;
    const __half* A = g_xh + (size_t)blockIdx.y * 128 * DIM;
    const __half* B = W    + (size_t)blockIdx.x * 128 * DIM;

    if (z == 2) {
        // V: write transposed into g_vth[batch][DIM][SEQ]
        const int batch = blockIdx.y >> 4;            // SEQ/128 = 16 blocks/batch
        const int seq0  = (blockIdx.y & 15) * 128;
        __half* C = g_vth + (size_t)batch * DIM * SEQ +
                    (size_t)blockIdx.x * 128 * SEQ + seq0;
        gemm_body<2>(A, B, C, DIM, DIM, SEQ, DIM / BK);
    } else {
        __half* out = (z == 0) ? g_qh : g_kh;
        __half* C = out + (size_t)blockIdx.y * 128 * DIM + (size_t)blockIdx.x * 128;
        gemm_body<1>(A, B, C, DIM, DIM, DIM, DIM / BK);
    }
}

__global__ void __launch_bounds__(256, 2) scores_gemm()
{
    const int bx = blockIdx.x, by = blockIdx.y, b = blockIdx.z;
    if (bx > by) return;   // strictly above causal diagonal: never read
    const __half* A = g_qh + ((size_t)b * SEQ + (size_t)by * 128) * DIM;
    const __half* B = g_kh + ((size_t)b * SEQ + (size_t)bx * 128) * DIM;
    float*        C = g_s  + ((size_t)b * SEQ + (size_t)by * 128) * SEQ + (size_t)bx * 128;
    gemm_body<0>(A, B, C, DIM, DIM, SEQ, DIM / BK);
}

__global__ void __launch_bounds__(256, 2) pv_gemm(float* __restrict__ out)
{
    const int bx = blockIdx.x, by = blockIdx.y, b = blockIdx.z;
    const __half* A = g_p   + ((size_t)b * SEQ + (size_t)by * 128) * SEQ;
    const __half* B = g_vth + (size_t)b * DIM * SEQ + (size_t)bx * 128 * SEQ;
    float*        C = out   + ((size_t)b * SEQ + (size_t)by * 128) * DIM + (size_t)bx * 128;
    gemm_body<0>(A, B, C, SEQ, SEQ, DIM, (by + 1) * (128 / BK));  // K to diag
}

// ---------------------------------------------------------------------------
// Data prep
// ---------------------------------------------------------------------------
__global__ void __launch_bounds__(256) x_to_half(const float* __restrict__ x)
{
    const int N4 = MTOT * DIM / 4;
    for (int i = blockIdx.x * blockDim.x + threadIdx.x; i < N4;
         i += gridDim.x * blockDim.x) {
        float4 v = ((const float4*)x)[i];
        __half2* dst = (__half2*)g_xh + 2 * i;
        dst[0] = __floats2half2_rn(v.x, v.y);
        dst[1] = __floats2half2_rn(v.z, v.w);
    }
}

// W [DIN][DOUT] -> W^T [DOUT][DIN] fp16. grid (32,32,3), block (32,8)
__global__ void wT_half(const float* __restrict__ Wq,
                        const float* __restrict__ Wk,
                        const float* __restrict__ Wv)
{
    __shared__ float t[32][33];
    const float* in   = (blockIdx.z == 0) ? Wq : (blockIdx.z == 1) ? Wk : Wv;
    __half*      out  = (blockIdx.z == 0) ? g_wqT : (blockIdx.z == 1) ? g_wkT : g_wvT;
    const int n0 = blockIdx.x * 32, k0 = blockIdx.y * 32;
    const int tx = threadIdx.x, ty = threadIdx.y;
#pragma unroll
    for (int i = 0; i < 32; i += 8)
        t[ty + i][tx] = in[(size_t)(k0 + ty + i) * DIM + n0 + tx];
    __syncthreads();
#pragma unroll
    for (int i = 0; i < 32; i += 8)
        out[(size_t)(n0 + ty + i) * DIM + k0 + tx] = __float2half_rn(t[tx][ty + i]);
}

// ---------------------------------------------------------------------------
// Causal softmax: fp32 scores in, fp16 probs out. Writes only the columns PV
// reads: [0, ceil(L/128)*128).
// ---------------------------------------------------------------------------
__global__ void __launch_bounds__(256) softmax_causal()
{
    __shared__ float red[256];
    const int row = blockIdx.x;
    const int b = row >> 11;
    const int i = row & (SEQ - 1);
    const float* srow = g_s + ((size_t)b * SEQ + i) * SEQ;
    __half*      prow = g_p + ((size_t)b * SEQ + i) * SEQ;
    const int L = i + 1;
    const int Lpad = (L + 127) & ~127;
    const int tid = threadIdx.x;

    float v[8];
    float m = -INFINITY;
#pragma unroll
    for (int u = 0; u < 8; u++) {
        int j = tid + u * 256;
        v[u] = (j < L) ? srow[j] * 0.03125f : -INFINITY;
        m = fmaxf(m, v[u]);
    }
    red[tid] = m;
    __syncthreads();
#pragma unroll
    for (int s = 128; s > 0; s >>= 1) {
        if (tid < s) red[tid] = fmaxf(red[tid], red[tid + s]);
        __syncthreads();
    }
    m = red[0];
    __syncthreads();

    float e[8];
    float sum = 0.0f;
#pragma unroll
    for (int u = 0; u < 8; u++) {
        int j = tid + u * 256;
        e[u] = (j < L) ? __expf(v[u] - m) : 0.0f;
        sum += e[u];
    }
    red[tid] = sum;
    __syncthreads();
#pragma unroll
    for (int s = 128; s > 0; s >>= 1) {
        if (tid < s) red[tid] += red[tid + s];
        __syncthreads();
    }
    const float inv = 1.0f / red[0];

#pragma unroll
    for (int u = 0; u < 8; u++) {
        int j = tid + u * 256;
        if (j < Lpad) prow[j] = __float2half_rn(e[u] * inv);   // j >= L -> 0
    }
}

// ---------------------------------------------------------------------------
extern "C" void kernel_launch(void* const* d_in, const int* in_sizes, int n_in,
                              void* d_out, int out_size)
{
    const float* x  = (const float*)d_in[0];
    const float* Wq = (const float*)d_in[1];
    const float* Wk = (const float*)d_in[2];
    const float* Wv = (const float*)d_in[3];
    float* out = (float*)d_out;

    cudaFuncSetAttribute(qkv_gemm,    cudaFuncAttributeMaxDynamicSharedMemorySize, SMEM_DYN);
    cudaFuncSetAttribute(scores_gemm, cudaFuncAttributeMaxDynamicSharedMemorySize, SMEM_DYN);
    cudaFuncSetAttribute(pv_gemm,     cudaFuncAttributeMaxDynamicSharedMemorySize, SMEM_DYN);

    dim3 gblk(256);
    dim3 tblk(32, 8);

    x_to_half<<<2048, 256>>>(x);
    wT_half<<<dim3(32, 32, 3), tblk>>>(Wq, Wk, Wv);
    qkv_gemm<<<dim3(DIM / 128, MTOT / 128, 3), gblk, SMEM_DYN>>>();
    scores_gemm<<<dim3(SEQ / 128, SEQ / 128, BATCH), gblk, SMEM_DYN>>>();
    softmax_causal<<<dim3(MTOT), 256>>>();
    pv_gemm<<<dim3(DIM / 128, SEQ / 128, BATCH), gblk, SMEM_DYN>>>(out);
}